// round 3
// baseline (speedup 1.0000x reference)
#include <cuda_runtime.h>
#include <cstdint>

// ---------------- problem constants ----------------
#define Hh 256
#define Ww 256
#define Bb 4
#define Cc 192
#define NHEAD 6
#define HD 32
#define NWMASK 1024          // windows per image
#define NWIN 4096            // total windows (B * 1024)
#define NTOK 64              // tokens per window
#define TOKALL (Bb*Hh*Ww)    // 262144 tokens
#define WINELEM (NTOK*Cc)    // 12288 floats per window

// ---------------- device scratch (no allocations allowed) ----------------
__device__ float g_xt[(size_t)TOKALL * Cc];   // x in BHWC
__device__ float g_ft[(size_t)TOKALL * Cc];   // feat in BHWC
__device__ float g_q [(size_t)NWIN * WINELEM];
__device__ float g_k [(size_t)NWIN * WINELEM];
__device__ float g_v [(size_t)NWIN * WINELEM];
__device__ float g_o [(size_t)NWIN * WINELEM];
__device__ float g_x1[(size_t)TOKALL * Cc];   // after first residual
__device__ float g_bias[NHEAD * NTOK * NTOK]; // expanded rel-pos bias

// ---------------- helpers ----------------
__device__ __forceinline__ float gelu_exact(float x) {
    return 0.5f * x * (1.0f + erff(x * 0.7071067811865475f));
}

// Block GEMM: C[64][192] += A(smem,[64][192]) @ W^T
// W global row-major, rows of length `wstride`, k window starts at `kbase`, K=192.
// 256 threads: warp w -> rows w*8..w*8+7 ; lane l -> cols l, l+32, ..., l+160.
// Wt smem tile: [32][200] (padded).
__device__ __forceinline__ void gemm192(const float* __restrict__ As,
                                        const float* __restrict__ Wg,
                                        int wstride, int kbase,
                                        float* __restrict__ Wt,
                                        float (&acc)[8][6], int tid) {
    const int lane = tid & 31;
    const int r0 = (tid >> 5) * 8;
    for (int kt = 0; kt < 6; ++kt) {
        const int k0 = kt * 32;
        __syncthreads();   // protect Wt from previous tile's readers
        #pragma unroll
        for (int it = 0; it < 24; ++it) {       // 24*256 = 6144 = 192*32
            int idx = tid + it * 256;
            int c = idx >> 5, kk = idx & 31;
            Wt[kk * 200 + c] = Wg[(size_t)c * wstride + kbase + k0 + kk];
        }
        __syncthreads();
        #pragma unroll
        for (int kk = 0; kk < 32; ++kk) {
            float a[8];
            #pragma unroll
            for (int i = 0; i < 8; ++i) a[i] = As[(r0 + i) * 192 + k0 + kk];
            #pragma unroll
            for (int j = 0; j < 6; ++j) {
                float bv = Wt[kk * 200 + lane + 32 * j];
                #pragma unroll
                for (int i = 0; i < 8; ++i) acc[i][j] = fmaf(a[i], bv, acc[i][j]);
            }
        }
    }
}

// ---------------- kernel 0: NCHW -> NHWC for x and feat ----------------
__global__ void k_transpose(const float* __restrict__ x, const float* __restrict__ f) {
    __shared__ float tile[32][33];
    int b = blockIdx.z >> 1;
    const float* src = (blockIdx.z & 1) ? f : x;
    float* dst = (blockIdx.z & 1) ? g_ft : g_xt;
    int hw0 = blockIdx.x * 32;
    int c0 = blockIdx.y * 32;
    #pragma unroll
    for (int i = threadIdx.y; i < 32; i += 8)
        tile[i][threadIdx.x] =
            src[((size_t)b * Cc + c0 + i) * (Hh * Ww) + hw0 + threadIdx.x];
    __syncthreads();
    #pragma unroll
    for (int i = threadIdx.y; i < 32; i += 8)
        dst[((size_t)b * (Hh * Ww) + hw0 + i) * Cc + c0 + threadIdx.x] =
            tile[threadIdx.x][i];
}

// ---------------- kernel 1: expand relative-position bias ----------------
__global__ void k_bias(const int* __restrict__ rel_index, const float* __restrict__ table) {
    int idx = blockIdx.x * blockDim.x + threadIdx.x;
    if (idx < NHEAD * NTOK * NTOK) {
        int h = idx / (NTOK * NTOK);
        int nm = idx % (NTOK * NTOK);
        g_bias[idx] = table[rel_index[nm] * NHEAD + h];
    }
}

// ---------------- kernel 2: per-window QKV projections ----------------
__global__ void k_qkv(const float* __restrict__ q_w, const float* __restrict__ q_b,
                      const float* __restrict__ kv_w, const float* __restrict__ kv_b) {
    extern __shared__ float sm[];
    float* A1 = sm;            // xw 64x192
    float* A2 = sm + 12288;    // fw 64x192
    float* Wt = sm + 24576;    // 32x200
    int wi = blockIdx.x;
    int b = wi >> 10, wl = wi & 1023, wh = wl >> 5, ww = wl & 31;
    int tid = threadIdx.x;

    for (int idx = tid; idx < WINELEM; idx += 256) {
        int n = idx / 192, c = idx - n * 192;
        int i = n >> 3, j = n & 7;
        int hh = (wh * 8 + i + 4) & 255;   // shift -4 (roll)
        int wp = (ww * 8 + j + 4) & 255;
        size_t off = (((size_t)b * Hh + hh) * Ww + wp) * Cc + c;
        A1[idx] = g_xt[off];
        A2[idx] = g_ft[off];
    }

    const int lane = tid & 31;
    const int r0 = (tid >> 5) * 8;
    const float scale = 0.17677669529663687f;   // 1/sqrt(32)
    float acc[8][6];

    // Q
    #pragma unroll
    for (int i = 0; i < 8; ++i)
        #pragma unroll
        for (int j = 0; j < 6; ++j) acc[i][j] = 0.f;
    gemm192(A1, q_w, 192, 0, Wt, acc, tid);
    #pragma unroll
    for (int i = 0; i < 8; ++i)
        #pragma unroll
        for (int j = 0; j < 6; ++j) {
            int c = lane + 32 * j;
            g_q[(size_t)wi * WINELEM + (r0 + i) * 192 + c] = (acc[i][j] + q_b[c]) * scale;
        }

    // K  (kv_w rows 0..191)
    #pragma unroll
    for (int i = 0; i < 8; ++i)
        #pragma unroll
        for (int j = 0; j < 6; ++j) acc[i][j] = 0.f;
    gemm192(A2, kv_w, 192, 0, Wt, acc, tid);
    #pragma unroll
    for (int i = 0; i < 8; ++i)
        #pragma unroll
        for (int j = 0; j < 6; ++j) {
            int c = lane + 32 * j;
            g_k[(size_t)wi * WINELEM + (r0 + i) * 192 + c] = acc[i][j] + kv_b[c];
        }

    // V  (kv_w rows 192..383)
    #pragma unroll
    for (int i = 0; i < 8; ++i)
        #pragma unroll
        for (int j = 0; j < 6; ++j) acc[i][j] = 0.f;
    gemm192(A2, kv_w + 192 * 192, 192, 0, Wt, acc, tid);
    #pragma unroll
    for (int i = 0; i < 8; ++i)
        #pragma unroll
        for (int j = 0; j < 6; ++j) {
            int c = lane + 32 * j;
            g_v[(size_t)wi * WINELEM + (r0 + i) * 192 + c] = acc[i][j] + kv_b[192 + c];
        }
}

// ---------------- kernel 3: windowed attention (one block per window*head) ----------------
__global__ void k_attn(const float* __restrict__ mask) {
    extern __shared__ float sm[];
    float* qs = sm;            // 64 x 33
    float* ks = sm + 2112;
    float* vs = sm + 4224;
    float* atts = sm + 6336;   // 64 x 65
    int bx = blockIdx.x;
    int wi = bx & 4095;
    int h = bx >> 12;
    int wl = wi & 1023;
    int tid = threadIdx.x;

    const size_t base = (size_t)wi * WINELEM + h * 32;
    for (int idx = tid; idx < 2048; idx += 128) {
        int n = idx >> 5, d = idx & 31;
        qs[n * 33 + d] = g_q[base + n * 192 + d];
        ks[n * 33 + d] = g_k[base + n * 192 + d];
        vs[n * 33 + d] = g_v[base + n * 192 + d];
    }
    __syncthreads();

    const int n = tid >> 1;
    const int mh = (tid & 1) * 32;
    for (int mm = 0; mm < 32; ++mm) {
        int m = mh + mm;
        float acc = 0.f;
        #pragma unroll
        for (int d = 0; d < 32; ++d) acc = fmaf(qs[n * 33 + d], ks[m * 33 + d], acc);
        atts[n * 65 + m] = acc;
    }
    __syncthreads();

    const float* bg = g_bias + h * 4096;
    const float* mg = mask + (size_t)wl * 4096;
    for (int idx = tid; idx < 4096; idx += 128)
        atts[(idx >> 6) * 65 + (idx & 63)] += bg[idx] + mg[idx];
    __syncthreads();

    if (tid < 64) {
        float mx = -1e30f;
        for (int m = 0; m < 64; ++m) mx = fmaxf(mx, atts[tid * 65 + m]);
        float s = 0.f;
        for (int m = 0; m < 64; ++m) {
            float e = __expf(atts[tid * 65 + m] - mx);
            atts[tid * 65 + m] = e;
            s += e;
        }
        float inv = 1.f / s;
        for (int m = 0; m < 64; ++m) atts[tid * 65 + m] *= inv;
    }
    __syncthreads();

    const int dbase = (tid & 1) * 16;
    float* og = g_o + base + n * 192;
    for (int dd = 0; dd < 16; ++dd) {
        int d = dbase + dd;
        float acc = 0.f;
        #pragma unroll
        for (int m = 0; m < 64; ++m) acc = fmaf(atts[n * 65 + m], vs[m * 33 + d], acc);
        og[d] = acc;
    }
}

// ---------------- kernel 4: proj -> reverse/roll -> merge -> LN -> residual ----------------
__global__ void k_projmerge(const float* __restrict__ proj_w, const float* __restrict__ proj_b,
                            const float* __restrict__ merge_w,
                            const float* __restrict__ g1, const float* __restrict__ b1) {
    extern __shared__ float sm[];
    float* A  = sm;            // attn out tile (later holds Z)
    float* Y  = sm + 12288;
    float* Wt = sm + 24576;    // 6400
    float* mu = sm + 30976;    // 64
    float* rs = sm + 31040;    // 64
    int wi = blockIdx.x;
    int tid = threadIdx.x;
    const int lane = tid & 31;
    const int r0 = (tid >> 5) * 8;

    for (int idx = tid; idx < WINELEM; idx += 256)
        A[idx] = g_o[(size_t)wi * WINELEM + idx];

    float acc[8][6];
    #pragma unroll
    for (int i = 0; i < 8; ++i)
        #pragma unroll
        for (int j = 0; j < 6; ++j) acc[i][j] = 0.f;
    gemm192(A, proj_w, 192, 0, Wt, acc, tid);     // internal syncs protect A load too
    #pragma unroll
    for (int i = 0; i < 8; ++i)
        #pragma unroll
        for (int j = 0; j < 6; ++j) {
            int c = lane + 32 * j;
            Y[(r0 + i) * 192 + c] = acc[i][j] + proj_b[c];
        }

    #pragma unroll
    for (int i = 0; i < 8; ++i)
        #pragma unroll
        for (int j = 0; j < 6; ++j) acc[i][j] = 0.f;
    gemm192(Y, merge_w, 192, 0, Wt, acc, tid);    // first internal sync makes Y visible
    #pragma unroll
    for (int i = 0; i < 8; ++i)
        #pragma unroll
        for (int j = 0; j < 6; ++j)
            A[(r0 + i) * 192 + lane + 32 * j] = acc[i][j];   // Z into A region (safe: gemm read Y/Wt)
    __syncthreads();

    if (tid < 64) {
        float s = 0.f, s2 = 0.f;
        for (int c = 0; c < 192; ++c) {
            float z = A[tid * 192 + c];
            s += z; s2 += z * z;
        }
        float m = s * (1.0f / 192.0f);
        float var = s2 * (1.0f / 192.0f) - m * m;
        mu[tid] = m;
        rs[tid] = rsqrtf(var + 1e-5f);
    }
    __syncthreads();

    int b = wi >> 10, wl = wi & 1023, wh = wl >> 5, ww = wl & 31;
    for (int idx = tid; idx < WINELEM; idx += 256) {
        int n = idx / 192, c = idx - n * 192;
        int i = n >> 3, j = n & 7;
        int hfin = (wh * 8 + i + 4) & 255;   // roll +4 back
        int wfin = (ww * 8 + j + 4) & 255;
        size_t off = (((size_t)b * Hh + hfin) * Ww + wfin) * Cc + c;
        float z = (A[idx] - mu[n]) * rs[n] * g1[c] + b1[c];
        g_x1[off] = g_xt[off] + z;
    }
}

// ---------------- kernel 5: fused MLP + LN + residual -> output ----------------
__global__ void k_mlp(const float* __restrict__ fc1_w, const float* __restrict__ fc1_b,
                      const float* __restrict__ fc2_w, const float* __restrict__ fc2_b,
                      const float* __restrict__ g2, const float* __restrict__ b2,
                      float* __restrict__ out) {
    extern __shared__ float sm[];
    float* A  = sm;            // x1 tile, kept for residual
    float* Hs = sm + 12288;    // hidden chunk / later Ms
    float* Wt = sm + 24576;
    float* mu = sm + 30976;
    float* rs = sm + 31040;
    int tid = threadIdx.x;
    const int lane = tid & 31;
    const int r0 = (tid >> 5) * 8;
    size_t tok0 = (size_t)blockIdx.x * 64;

    for (int idx = tid; idx < WINELEM; idx += 256)
        A[idx] = g_x1[tok0 * Cc + idx];

    float macc[8][6];
    #pragma unroll
    for (int i = 0; i < 8; ++i)
        #pragma unroll
        for (int j = 0; j < 6; ++j) macc[i][j] = 0.f;

    for (int ch = 0; ch < 4; ++ch) {
        float hacc[8][6];
        #pragma unroll
        for (int i = 0; i < 8; ++i)
            #pragma unroll
            for (int j = 0; j < 6; ++j) hacc[i][j] = 0.f;
        gemm192(A, fc1_w + (size_t)ch * 192 * 192, 192, 0, Wt, hacc, tid);
        #pragma unroll
        for (int i = 0; i < 8; ++i)
            #pragma unroll
            for (int j = 0; j < 6; ++j) {
                int c = lane + 32 * j;
                float xv = hacc[i][j] + fc1_b[ch * 192 + c];
                Hs[(r0 + i) * 192 + c] = gelu_exact(xv);
            }
        // gemm192's first internal __syncthreads makes Hs visible before reads
        gemm192(Hs, fc2_w, 768, ch * 192, Wt, macc, tid);
    }
    __syncthreads();
    #pragma unroll
    for (int i = 0; i < 8; ++i)
        #pragma unroll
        for (int j = 0; j < 6; ++j) {
            int c = lane + 32 * j;
            Hs[(r0 + i) * 192 + c] = macc[i][j] + fc2_b[c];
        }
    __syncthreads();

    if (tid < 64) {
        float s = 0.f, s2 = 0.f;
        for (int c = 0; c < 192; ++c) {
            float z = Hs[tid * 192 + c];
            s += z; s2 += z * z;
        }
        float m = s * (1.0f / 192.0f);
        float var = s2 * (1.0f / 192.0f) - m * m;
        mu[tid] = m;
        rs[tid] = rsqrtf(var + 1e-5f);
    }
    __syncthreads();

    for (int idx = tid; idx < WINELEM; idx += 256) {
        int n = idx / 192, c = idx - n * 192;
        out[tok0 * Cc + idx] = A[idx] + (Hs[idx] - mu[n]) * rs[n] * g2[c] + b2[c];
    }
}

// ---------------- launch ----------------
extern "C" void kernel_launch(void* const* d_in, const int* in_sizes, int n_in,
                              void* d_out, int out_size) {
    const float* x        = (const float*)d_in[0];
    const float* feat     = (const float*)d_in[1];
    const float* attn_mask= (const float*)d_in[2];
    const int*   rel_index= (const int*)  d_in[3];
    const float* rel_tab  = (const float*)d_in[4];
    const float* q_w      = (const float*)d_in[5];
    const float* q_b      = (const float*)d_in[6];
    const float* kv_w     = (const float*)d_in[7];
    const float* kv_b     = (const float*)d_in[8];
    const float* proj_w   = (const float*)d_in[9];
    const float* proj_b   = (const float*)d_in[10];
    const float* merge_w  = (const float*)d_in[11];
    const float* n1g      = (const float*)d_in[12];
    const float* n1b      = (const float*)d_in[13];
    const float* n2g      = (const float*)d_in[14];
    const float* n2b      = (const float*)d_in[15];
    const float* fc1_w    = (const float*)d_in[16];
    const float* fc1_b    = (const float*)d_in[17];
    const float* fc2_w    = (const float*)d_in[18];
    const float* fc2_b    = (const float*)d_in[19];
    float* out = (float*)d_out;

    const int SMEM_GEMM = (12288 * 2 + 6400 + 128) * 4;   // 124,928 B
    const int SMEM_ATTN = (2112 * 3 + 4160) * 4;          //  41,984 B
    cudaFuncSetAttribute(k_qkv,       cudaFuncAttributeMaxDynamicSharedMemorySize, SMEM_GEMM);
    cudaFuncSetAttribute(k_projmerge, cudaFuncAttributeMaxDynamicSharedMemorySize, SMEM_GEMM);
    cudaFuncSetAttribute(k_mlp,       cudaFuncAttributeMaxDynamicSharedMemorySize, SMEM_GEMM);
    cudaFuncSetAttribute(k_attn,      cudaFuncAttributeMaxDynamicSharedMemorySize, SMEM_ATTN);

    k_transpose<<<dim3(2048, 6, 8), dim3(32, 8)>>>(x, feat);
    k_bias<<<96, 256>>>(rel_index, rel_tab);
    k_qkv<<<NWIN, 256, SMEM_GEMM>>>(q_w, q_b, kv_w, kv_b);
    k_attn<<<NWIN * NHEAD, 128, SMEM_ATTN>>>(attn_mask);
    k_projmerge<<<NWIN, 256, SMEM_GEMM>>>(proj_w, proj_b, merge_w, n1g, n1b);
    k_mlp<<<TOKALL / 64, 256, SMEM_GEMM>>>(fc1_w, fc1_b, fc2_w, fc2_b, n2g, n2b, out);
}

// round 5
// speedup vs baseline: 1.4526x; 1.4526x over previous
#include <cuda_runtime.h>
#include <cuda_bf16.h>
#include <cstdint>

// ---------------- problem constants ----------------
#define Hh 256
#define Ww 256
#define Bb 4
#define Cc 192
#define NHEAD 6
#define NWIN 4096            // total windows (B * 1024)
#define NTOK 64              // tokens per window
#define TOKALL (Bb*Hh*Ww)    // 262144 tokens
#define WINELEM (NTOK*Cc)    // 12288 floats per window

// weight-split offsets (elements)
#define OQ  0
#define OKV 36864
#define OP  110592
#define OM  147456
#define OF1 184320
#define OF2 331776
#define WTOT 479232

// ---------------- device scratch (no allocations allowed) ----------------
__device__ float g_xt[(size_t)TOKALL * Cc];   // x in BHWC
__device__ float g_ft[(size_t)TOKALL * Cc];   // feat in BHWC
__device__ float g_q [(size_t)NWIN * WINELEM];
__device__ float g_k [(size_t)NWIN * WINELEM];
__device__ float g_v [(size_t)NWIN * WINELEM];
__device__ float g_o [(size_t)NWIN * WINELEM];
__device__ float g_x1[(size_t)TOKALL * Cc];   // after first residual
__device__ float g_bias[NHEAD * NTOK * NTOK]; // expanded rel-pos bias
__device__ __align__(16) __nv_bfloat16 g_wh[WTOT];  // all weights, bf16 hi
__device__ __align__(16) __nv_bfloat16 g_wl[WTOT];  // all weights, bf16 lo

// ---------------- helpers ----------------
__device__ __forceinline__ float gelu_fast(float x) {
    float z = x * 0.7071067811865475f;
    float az = fabsf(z);
    float t = __fdividef(1.0f, fmaf(0.3275911f, az, 1.0f));
    float p = t * (0.254829592f + t * (-0.284496736f + t * (1.421413741f +
              t * (-1.453152027f + t * 1.061405429f))));
    float e = __expf(-az * az);
    float erfv = 1.0f - p * e;
    erfv = copysignf(erfv, z);
    return 0.5f * x * (1.0f + erfv);
}

__device__ __forceinline__ uint32_t smem_u32(const void* p) {
    uint32_t a;
    asm("{ .reg .u64 t; cvta.to.shared.u64 t, %1; cvt.u32.u64 %0, t; }" : "=r"(a) : "l"(p));
    return a;
}

__device__ __forceinline__ void split2(float v0, float v1, uint32_t& hp, uint32_t& lp) {
    __nv_bfloat16 h0 = __float2bfloat16(v0);
    __nv_bfloat16 h1 = __float2bfloat16(v1);
    __nv_bfloat16 l0 = __float2bfloat16(v0 - __bfloat162float(h0));
    __nv_bfloat16 l1 = __float2bfloat16(v1 - __bfloat162float(h1));
    hp = (uint32_t)__bfloat16_as_ushort(h0) | ((uint32_t)__bfloat16_as_ushort(h1) << 16);
    lp = (uint32_t)__bfloat16_as_ushort(l0) | ((uint32_t)__bfloat16_as_ushort(l1) << 16);
}

__device__ __forceinline__ void ldsm_x4(uint32_t (&r)[4], uint32_t a) {
    asm volatile("ldmatrix.sync.aligned.m8n8.x4.shared.b16 {%0,%1,%2,%3}, [%4];"
        : "=r"(r[0]), "=r"(r[1]), "=r"(r[2]), "=r"(r[3]) : "r"(a));
}

__device__ __forceinline__ void mma16816(float (&c)[4], const uint32_t (&a)[4],
                                         uint32_t b0, uint32_t b1) {
    asm volatile("mma.sync.aligned.m16n8k16.row.col.f32.bf16.bf16.f32 "
        "{%0,%1,%2,%3}, {%4,%5,%6,%7}, {%8,%9}, {%0,%1,%2,%3};"
        : "+f"(c[0]), "+f"(c[1]), "+f"(c[2]), "+f"(c[3])
        : "r"(a[0]), "r"(a[1]), "r"(a[2]), "r"(a[3]), "r"(b0), "r"(b1));
}

// Warp GEMM: C[16][NT2*16] += A[16][KS*16] @ W^T, bf16 hi/lo split (3 terms).
// aH/aL point at this warp's A row block; wH/wL at W n-row 0. Strides in bf16 elems.
template<int KS, int NT2, int AS, int WS>
__device__ __forceinline__ void wgemm(uint32_t aH, uint32_t aL,
                                      uint32_t wH, uint32_t wL,
                                      float (*c)[4], int lane) {
    const uint32_t aoff = (uint32_t)(((lane & 15) * AS + ((lane >> 4) << 3)) * 2);
    const uint32_t woff = (uint32_t)(((((lane >> 4) << 3) + (lane & 7)) * WS + (lane & 8)) * 2);
    aH += aoff; aL += aoff; wH += woff; wL += woff;
    for (int ks = 0; ks < KS; ++ks) {
        uint32_t ah[4], al[4];
        ldsm_x4(ah, aH + ks * 32);
        ldsm_x4(al, aL + ks * 32);
        #pragma unroll
        for (int p = 0; p < NT2; ++p) {
            uint32_t bh[4], bl[4];
            ldsm_x4(bh, wH + p * (16 * WS * 2) + ks * 32);
            ldsm_x4(bl, wL + p * (16 * WS * 2) + ks * 32);
            mma16816(c[2*p],   ah, bh[0], bh[1]);
            mma16816(c[2*p],   al, bh[0], bh[1]);
            mma16816(c[2*p],   ah, bl[0], bl[1]);
            mma16816(c[2*p+1], ah, bh[2], bh[3]);
            mma16816(c[2*p+1], al, bh[2], bh[3]);
            mma16816(c[2*p+1], ah, bl[2], bl[3]);
        }
    }
}

// stage pre-split weights (bf16) into smem, row stride dstride
__device__ __forceinline__ void stageW(char* dh, char* dl,
        const __nv_bfloat16* sh, const __nv_bfloat16* sl,
        int rows, int ku4, int srck, int koff, int dstride, int tid) {
    int tot = rows * ku4;
    for (int i = tid; i < tot; i += 256) {
        int r = i / ku4, q = i - r * ku4;
        size_t s = (size_t)r * srck + koff + q * 8;
        size_t d = ((size_t)r * dstride + q * 8) * 2;
        *(uint4*)(dh + d) = *(const uint4*)(sh + s);
        *(uint4*)(dl + d) = *(const uint4*)(sl + s);
    }
}

// stage fp32 activations -> split bf16 hi/lo smem (stride 200), linear source
__device__ __forceinline__ void stage_linear(char* dh, char* dl, const float* src, int tid) {
    for (int i = tid; i < 128 * 96; i += 256) {
        int r = i / 96, cp = (i - r * 96) * 2;
        float2 v = *(const float2*)(src + (size_t)r * 192 + cp);
        uint32_t hp, lp; split2(v.x, v.y, hp, lp);
        size_t d = ((size_t)r * 200 + cp) * 2;
        *(uint32_t*)(dh + d) = hp;
        *(uint32_t*)(dl + d) = lp;
    }
}

// stage with shifted-window gather (roll -4), 2 windows per CTA
__device__ __forceinline__ void stage_gather(char* dh, char* dl, const float* src,
                                             int w0, int tid) {
    for (int i = tid; i < 128 * 96; i += 256) {
        int r = i / 96, cp = (i - r * 96) * 2;
        int win = w0 + (r >> 6);
        int b = win >> 10, wlr = win & 1023, wh = wlr >> 5, ww = wlr & 31;
        int n = r & 63, ii = n >> 3, jj = n & 7;
        int hh = (wh * 8 + ii + 4) & 255, wp = (ww * 8 + jj + 4) & 255;
        size_t off = (((size_t)b * 256 + hh) * 256 + wp) * 192 + cp;
        float2 v = *(const float2*)(src + off);
        uint32_t hp, lp; split2(v.x, v.y, hp, lp);
        size_t d = ((size_t)r * 200 + cp) * 2;
        *(uint32_t*)(dh + d) = hp;
        *(uint32_t*)(dl + d) = lp;
    }
}

// ---------------- kernel 0: NCHW -> NHWC ----------------
__global__ void k_transpose(const float* __restrict__ x, const float* __restrict__ f) {
    __shared__ float tile[32][33];
    int b = blockIdx.z >> 1;
    const float* src = (blockIdx.z & 1) ? f : x;
    float* dst = (blockIdx.z & 1) ? g_ft : g_xt;
    int hw0 = blockIdx.x * 32;
    int c0 = blockIdx.y * 32;
    #pragma unroll
    for (int i = threadIdx.y; i < 32; i += 8)
        tile[i][threadIdx.x] =
            src[((size_t)b * Cc + c0 + i) * (Hh * Ww) + hw0 + threadIdx.x];
    __syncthreads();
    #pragma unroll
    for (int i = threadIdx.y; i < 32; i += 8)
        dst[((size_t)b * (Hh * Ww) + hw0 + i) * Cc + c0 + threadIdx.x] =
            tile[threadIdx.x][i];
}

// ---------------- kernel 1: expand relative-position bias ----------------
__global__ void k_bias(const int* __restrict__ rel_index, const float* __restrict__ table) {
    int idx = blockIdx.x * blockDim.x + threadIdx.x;
    if (idx < NHEAD * NTOK * NTOK) {
        int h = idx / (NTOK * NTOK);
        int nm = idx % (NTOK * NTOK);
        g_bias[idx] = table[rel_index[nm] * NHEAD + h];
    }
}

// ---------------- kernel 1b: split ALL weights to bf16 hi/lo ----------------
__global__ void k_wsplit(const float* __restrict__ q_w, const float* __restrict__ kv_w,
                         const float* __restrict__ proj_w, const float* __restrict__ merge_w,
                         const float* __restrict__ fc1_w, const float* __restrict__ fc2_w) {
    int i = blockIdx.x * 256 + threadIdx.x;
    if (i >= WTOT) return;
    float v;
    if (i < OKV)       v = q_w[i];
    else if (i < OP)   v = kv_w[i - OKV];
    else if (i < OM)   v = proj_w[i - OP];
    else if (i < OF1)  v = merge_w[i - OM];
    else if (i < OF2)  v = fc1_w[i - OF1];
    else               v = fc2_w[i - OF2];
    __nv_bfloat16 h = __float2bfloat16(v);
    g_wh[i] = h;
    g_wl[i] = __float2bfloat16(v - __bfloat162float(h));
}

// ---------------- kernel 2: QKV projections via mma.sync ----------------
// smem: Ahi 0..51200, Alo 51200.., Whi 102400.. (96x200), Wlo 140800..
#define QKV_SMEM 179200
__global__ void __launch_bounds__(256, 1)
k_qkv_tc(const float* __restrict__ q_b, const float* __restrict__ kv_b) {
    extern __shared__ char smc[];
    const uint32_t sb = smem_u32(smc);
    char* A_HI = smc;            char* A_LO = smc + 51200;
    char* W_HI = smc + 102400;   char* W_LO = smc + 140800;
    const uint32_t aHI = sb, aLO = sb + 51200, wHI = sb + 102400, wLO = sb + 140800;
    int tid = threadIdx.x, wid = tid >> 5, lane = tid & 31;
    int gid = lane >> 2, tig = lane & 3;
    size_t tok0 = (size_t)blockIdx.x * 128;
    int w0 = blockIdx.x * 2;
    const float scale = 0.17677669529663687f;
    const uint32_t aW = aHI + (uint32_t)(wid * 16 * 400);
    const uint32_t aWl = aLO + (uint32_t)(wid * 16 * 400);

    stage_gather(A_HI, A_LO, g_xt, w0, tid);

    // Q
    for (int ch = 0; ch < 2; ++ch) {
        __syncthreads();
        stageW(W_HI, W_LO, g_wh + OQ + (size_t)ch * 96 * 192, g_wl + OQ + (size_t)ch * 96 * 192,
               96, 24, 192, 0, 200, tid);
        __syncthreads();
        float c[12][4];
        #pragma unroll
        for (int i = 0; i < 12; ++i) { c[i][0]=c[i][1]=c[i][2]=c[i][3]=0.f; }
        wgemm<12, 6, 200, 200>(aW, aWl, wHI, wLO, c, lane);
        size_t rA = tok0 + wid * 16 + gid;
        #pragma unroll
        for (int nt = 0; nt < 12; ++nt) {
            int col = ch * 96 + nt * 8 + 2 * tig;
            float2 o0 = make_float2((c[nt][0] + q_b[col]) * scale, (c[nt][1] + q_b[col+1]) * scale);
            float2 o1 = make_float2((c[nt][2] + q_b[col]) * scale, (c[nt][3] + q_b[col+1]) * scale);
            *(float2*)(g_q + rA * 192 + col) = o0;
            *(float2*)(g_q + (rA + 8) * 192 + col) = o1;
        }
    }

    __syncthreads();                    // all warps done with A before restage
    stage_gather(A_HI, A_LO, g_ft, w0, tid);

    // K then V
    for (int kv = 0; kv < 2; ++kv) {
        float* dst = kv ? g_v : g_k;
        const float* bias = kv_b + kv * 192;
        for (int ch = 0; ch < 2; ++ch) {
            __syncthreads();
            size_t wo = OKV + (size_t)(kv * 192 + ch * 96) * 192;
            stageW(W_HI, W_LO, g_wh + wo, g_wl + wo, 96, 24, 192, 0, 200, tid);
            __syncthreads();
            float c[12][4];
            #pragma unroll
            for (int i = 0; i < 12; ++i) { c[i][0]=c[i][1]=c[i][2]=c[i][3]=0.f; }
            wgemm<12, 6, 200, 200>(aW, aWl, wHI, wLO, c, lane);
            size_t rA = tok0 + wid * 16 + gid;
            #pragma unroll
            for (int nt = 0; nt < 12; ++nt) {
                int col = ch * 96 + nt * 8 + 2 * tig;
                float2 o0 = make_float2(c[nt][0] + bias[col], c[nt][1] + bias[col+1]);
                float2 o1 = make_float2(c[nt][2] + bias[col], c[nt][3] + bias[col+1]);
                *(float2*)(dst + rA * 192 + col) = o0;
                *(float2*)(dst + (rA + 8) * 192 + col) = o1;
            }
        }
    }
}

// ---------------- kernel 3: windowed attention (fp32, unchanged) ----------------
__global__ void k_attn(const float* __restrict__ mask) {
    extern __shared__ float sm[];
    float* qs = sm;
    float* ks = sm + 2112;
    float* vs = sm + 4224;
    float* atts = sm + 6336;
    int bx = blockIdx.x;
    int wi = bx & 4095;
    int h = bx >> 12;
    int wl = wi & 1023;
    int tid = threadIdx.x;

    const size_t base = (size_t)wi * WINELEM + h * 32;
    for (int idx = tid; idx < 2048; idx += 128) {
        int n = idx >> 5, d = idx & 31;
        qs[n * 33 + d] = g_q[base + n * 192 + d];
        ks[n * 33 + d] = g_k[base + n * 192 + d];
        vs[n * 33 + d] = g_v[base + n * 192 + d];
    }
    __syncthreads();

    const int n = tid >> 1;
    const int mh = (tid & 1) * 32;
    for (int mm = 0; mm < 32; ++mm) {
        int m = mh + mm;
        float acc = 0.f;
        #pragma unroll
        for (int d = 0; d < 32; ++d) acc = fmaf(qs[n * 33 + d], ks[m * 33 + d], acc);
        atts[n * 65 + m] = acc;
    }
    __syncthreads();

    const float* bg = g_bias + h * 4096;
    const float* mg = mask + (size_t)wl * 4096;
    for (int idx = tid; idx < 4096; idx += 128)
        atts[(idx >> 6) * 65 + (idx & 63)] += bg[idx] + mg[idx];
    __syncthreads();

    if (tid < 64) {
        float mx = -1e30f;
        for (int m = 0; m < 64; ++m) mx = fmaxf(mx, atts[tid * 65 + m]);
        float s = 0.f;
        for (int m = 0; m < 64; ++m) {
            float e = __expf(atts[tid * 65 + m] - mx);
            atts[tid * 65 + m] = e;
            s += e;
        }
        float inv = 1.f / s;
        for (int m = 0; m < 64; ++m) atts[tid * 65 + m] *= inv;
    }
    __syncthreads();

    const int dbase = (tid & 1) * 16;
    float* og = g_o + base + n * 192;
    for (int dd = 0; dd < 16; ++dd) {
        int d = dbase + dd;
        float acc = 0.f;
        #pragma unroll
        for (int m = 0; m < 64; ++m) acc = fmaf(atts[n * 65 + m], vs[m * 33 + d], acc);
        og[d] = acc;
    }
}

// ---------------- kernel 4: proj -> merge -> LN -> residual (mma.sync) ----------------
#define PM_SMEM 179200
__global__ void __launch_bounds__(256, 1)
k_projmerge_tc(const float* __restrict__ proj_b,
               const float* __restrict__ g1, const float* __restrict__ b1) {
    extern __shared__ char smc[];
    const uint32_t sb = smem_u32(smc);
    char* A_HI = smc;            char* A_LO = smc + 51200;
    char* W_HI = smc + 102400;   char* W_LO = smc + 140800;
    const uint32_t aHI = sb, aLO = sb + 51200, wHI = sb + 102400, wLO = sb + 140800;
    int tid = threadIdx.x, wid = tid >> 5, lane = tid & 31;
    int gid = lane >> 2, tig = lane & 3;
    size_t tok0 = (size_t)blockIdx.x * 128;
    const uint32_t aW = aHI + (uint32_t)(wid * 16 * 400);
    const uint32_t aWl = aLO + (uint32_t)(wid * 16 * 400);
    int lrA = wid * 16 + gid, lrB = lrA + 8;

    stage_linear(A_HI, A_LO, g_o + tok0 * 192, tid);

    // GEMM1: Y = A @ proj^T + proj_b  (hold both chunks in regs)
    float c1[2][12][4];
    for (int ch = 0; ch < 2; ++ch) {
        __syncthreads();
        size_t wo = OP + (size_t)ch * 96 * 192;
        stageW(W_HI, W_LO, g_wh + wo, g_wl + wo, 96, 24, 192, 0, 200, tid);
        __syncthreads();
        #pragma unroll
        for (int i = 0; i < 12; ++i) { c1[ch][i][0]=c1[ch][i][1]=c1[ch][i][2]=c1[ch][i][3]=0.f; }
        wgemm<12, 6, 200, 200>(aW, aWl, wHI, wLO, c1[ch], lane);
    }
    __syncthreads();   // everyone done reading A
    // write Y (split) into A region — each warp writes only its own rows
    #pragma unroll
    for (int ch = 0; ch < 2; ++ch)
        #pragma unroll
        for (int nt = 0; nt < 12; ++nt) {
            int col = ch * 96 + nt * 8 + 2 * tig;
            uint32_t hp, lp;
            split2(c1[ch][nt][0] + proj_b[col], c1[ch][nt][1] + proj_b[col+1], hp, lp);
            size_t dA = ((size_t)lrA * 200 + col) * 2;
            *(uint32_t*)(A_HI + dA) = hp; *(uint32_t*)(A_LO + dA) = lp;
            split2(c1[ch][nt][2] + proj_b[col], c1[ch][nt][3] + proj_b[col+1], hp, lp);
            size_t dB = ((size_t)lrB * 200 + col) * 2;
            *(uint32_t*)(A_HI + dB) = hp; *(uint32_t*)(A_LO + dB) = lp;
        }
    __syncwarp();

    // GEMM2: Z = Y @ merge^T (no bias)
    float c2[2][12][4];
    for (int ch = 0; ch < 2; ++ch) {
        __syncthreads();
        size_t wo = OM + (size_t)ch * 96 * 192;
        stageW(W_HI, W_LO, g_wh + wo, g_wl + wo, 96, 24, 192, 0, 200, tid);
        __syncthreads();
        #pragma unroll
        for (int i = 0; i < 12; ++i) { c2[ch][i][0]=c2[ch][i][1]=c2[ch][i][2]=c2[ch][i][3]=0.f; }
        wgemm<12, 6, 200, 200>(aW, aWl, wHI, wLO, c2[ch], lane);
    }

    // LN over rows (quad shuffle reduce), then roll/scatter + residual
    float sA = 0.f, qA = 0.f, sB = 0.f, qB = 0.f;
    #pragma unroll
    for (int ch = 0; ch < 2; ++ch)
        #pragma unroll
        for (int nt = 0; nt < 12; ++nt) {
            sA += c2[ch][nt][0] + c2[ch][nt][1];
            qA += c2[ch][nt][0]*c2[ch][nt][0] + c2[ch][nt][1]*c2[ch][nt][1];
            sB += c2[ch][nt][2] + c2[ch][nt][3];
            qB += c2[ch][nt][2]*c2[ch][nt][2] + c2[ch][nt][3]*c2[ch][nt][3];
        }
    #pragma unroll
    for (int d = 1; d <= 2; d <<= 1) {
        sA += __shfl_xor_sync(0xffffffffu, sA, d);
        qA += __shfl_xor_sync(0xffffffffu, qA, d);
        sB += __shfl_xor_sync(0xffffffffu, sB, d);
        qB += __shfl_xor_sync(0xffffffffu, qB, d);
    }
    float muA = sA * (1.f/192.f), rsA = rsqrtf(qA * (1.f/192.f) - muA*muA + 1e-5f);
    float muB = sB * (1.f/192.f), rsB = rsqrtf(qB * (1.f/192.f) - muB*muB + 1e-5f);

    auto rowoff = [&](int lr) -> size_t {
        int win = blockIdx.x * 2 + (lr >> 6);
        int b = win >> 10, wlr = win & 1023, wh = wlr >> 5, ww = wlr & 31;
        int n = lr & 63, ii = n >> 3, jj = n & 7;
        int hf = (wh * 8 + ii + 4) & 255, wf = (ww * 8 + jj + 4) & 255;
        return (((size_t)b * 256 + hf) * 256 + wf) * 192;
    };
    size_t roA = rowoff(lrA), roB = rowoff(lrB);

    #pragma unroll
    for (int ch = 0; ch < 2; ++ch)
        #pragma unroll
        for (int nt = 0; nt < 12; ++nt) {
            int col = ch * 96 + nt * 8 + 2 * tig;
            float2 xa = *(const float2*)(g_xt + roA + col);
            float2 za;
            za.x = xa.x + (c2[ch][nt][0] - muA) * rsA * g1[col]   + b1[col];
            za.y = xa.y + (c2[ch][nt][1] - muA) * rsA * g1[col+1] + b1[col+1];
            *(float2*)(g_x1 + roA + col) = za;
            float2 xb = *(const float2*)(g_xt + roB + col);
            float2 zb;
            zb.x = xb.x + (c2[ch][nt][2] - muB) * rsB * g1[col]   + b1[col];
            zb.y = xb.y + (c2[ch][nt][3] - muB) * rsB * g1[col+1] + b1[col+1];
            *(float2*)(g_x1 + roB + col) = zb;
        }
}

// ---------------- kernel 5: MLP (fc1+GELU+fc2) + LN + residual (mma.sync) ----------------
// smem: Ahi 0 (51200) Alo 51200 | Hhi 102400 (18432) Hlo 120832 | Whi 139264 (27648) Wlo 166912
#define MLP_SMEM 194560
__global__ void __launch_bounds__(256, 1)
k_mlp_tc(const float* __restrict__ fc1_b, const float* __restrict__ fc2_b,
         const float* __restrict__ g2, const float* __restrict__ b2,
         float* __restrict__ out) {
    extern __shared__ char smc[];
    const uint32_t sb = smem_u32(smc);
    char* A_HI = smc;            char* A_LO = smc + 51200;
    char* H_HI = smc + 102400;   char* H_LO = smc + 120832;
    char* W_HI = smc + 139264;   char* W_LO = smc + 166912;
    const uint32_t aHI = sb, aLO = sb + 51200;
    const uint32_t hHI = sb + 102400, hLO = sb + 120832;
    const uint32_t wHI = sb + 139264, wLO = sb + 166912;
    int tid = threadIdx.x, wid = tid >> 5, lane = tid & 31;
    int gid = lane >> 2, tig = lane & 3;
    size_t tok0 = (size_t)blockIdx.x * 128;
    const uint32_t aW = aHI + (uint32_t)(wid * 16 * 400);
    const uint32_t aWl = aLO + (uint32_t)(wid * 16 * 400);
    const uint32_t hW = hHI + (uint32_t)(wid * 16 * 144);
    const uint32_t hWl = hLO + (uint32_t)(wid * 16 * 144);
    int lrA = wid * 16 + gid, lrB = lrA + 8;

    stage_linear(A_HI, A_LO, g_x1 + tok0 * 192, tid);

    float cf2[2][12][4];
    #pragma unroll
    for (int p = 0; p < 2; ++p)
        #pragma unroll
        for (int i = 0; i < 12; ++i) { cf2[p][i][0]=cf2[p][i][1]=cf2[p][i][2]=cf2[p][i][3]=0.f; }

    for (int ck = 0; ck < 12; ++ck) {
        // fc1 chunk: H[:,64] = gelu(A @ W1_ck^T + b1_ck)
        __syncthreads();
        size_t wo = OF1 + (size_t)ck * 64 * 192;
        stageW(W_HI, W_LO, g_wh + wo, g_wl + wo, 64, 24, 192, 0, 200, tid);
        __syncthreads();
        float c1[8][4];
        #pragma unroll
        for (int i = 0; i < 8; ++i) { c1[i][0]=c1[i][1]=c1[i][2]=c1[i][3]=0.f; }
        wgemm<12, 4, 200, 200>(aW, aWl, wHI, wLO, c1, lane);
        #pragma unroll
        for (int nt = 0; nt < 8; ++nt) {
            int col = nt * 8 + 2 * tig;
            int bc = ck * 64 + col;
            uint32_t hp, lp;
            split2(gelu_fast(c1[nt][0] + fc1_b[bc]), gelu_fast(c1[nt][1] + fc1_b[bc+1]), hp, lp);
            size_t dA = ((size_t)lrA * 72 + col) * 2;
            *(uint32_t*)(H_HI + dA) = hp; *(uint32_t*)(H_LO + dA) = lp;
            split2(gelu_fast(c1[nt][2] + fc1_b[bc]), gelu_fast(c1[nt][3] + fc1_b[bc+1]), hp, lp);
            size_t dB = ((size_t)lrB * 72 + col) * 2;
            *(uint32_t*)(H_HI + dB) = hp; *(uint32_t*)(H_LO + dB) = lp;
        }
        __syncwarp();
        // fc2 k-slice: accumulate over both n-halves
        __syncthreads();
        stageW(W_HI, W_LO, g_wh + OF2, g_wl + OF2, 192, 8, 768, ck * 64, 72, tid);
        __syncthreads();
        wgemm<4, 6, 72, 72>(hW, hWl, wHI, wLO, cf2[0], lane);
        wgemm<4, 6, 72, 72>(hW, hWl, wHI + 96u * 144u, wLO + 96u * 144u, cf2[1], lane);
    }

    // LN + residual epilogue
    float sA = 0.f, qA = 0.f, sB = 0.f, qB = 0.f;
    #pragma unroll
    for (int p = 0; p < 2; ++p)
        #pragma unroll
        for (int nt = 0; nt < 12; ++nt) {
            int col = p * 96 + nt * 8 + 2 * tig;
            float z0 = cf2[p][nt][0] + fc2_b[col];
            float z1 = cf2[p][nt][1] + fc2_b[col+1];
            float z2 = cf2[p][nt][2] + fc2_b[col];
            float z3 = cf2[p][nt][3] + fc2_b[col+1];
            sA += z0 + z1; qA += z0*z0 + z1*z1;
            sB += z2 + z3; qB += z2*z2 + z3*z3;
        }
    #pragma unroll
    for (int d = 1; d <= 2; d <<= 1) {
        sA += __shfl_xor_sync(0xffffffffu, sA, d);
        qA += __shfl_xor_sync(0xffffffffu, qA, d);
        sB += __shfl_xor_sync(0xffffffffu, sB, d);
        qB += __shfl_xor_sync(0xffffffffu, qB, d);
    }
    float muA = sA * (1.f/192.f), rsA = rsqrtf(qA * (1.f/192.f) - muA*muA + 1e-5f);
    float muB = sB * (1.f/192.f), rsB = rsqrtf(qB * (1.f/192.f) - muB*muB + 1e-5f);

    size_t grA = (tok0 + lrA) * 192, grB = (tok0 + lrB) * 192;
    #pragma unroll
    for (int p = 0; p < 2; ++p)
        #pragma unroll
        for (int nt = 0; nt < 12; ++nt) {
            int col = p * 96 + nt * 8 + 2 * tig;
            float z0 = cf2[p][nt][0] + fc2_b[col];
            float z1 = cf2[p][nt][1] + fc2_b[col+1];
            float z2 = cf2[p][nt][2] + fc2_b[col];
            float z3 = cf2[p][nt][3] + fc2_b[col+1];
            float2 xa = *(const float2*)(g_x1 + grA + col);
            float2 oa;
            oa.x = xa.x + (z0 - muA) * rsA * g2[col]   + b2[col];
            oa.y = xa.y + (z1 - muA) * rsA * g2[col+1] + b2[col+1];
            *(float2*)(out + grA + col) = oa;
            float2 xb = *(const float2*)(g_x1 + grB + col);
            float2 ob;
            ob.x = xb.x + (z2 - muB) * rsB * g2[col]   + b2[col];
            ob.y = xb.y + (z3 - muB) * rsB * g2[col+1] + b2[col+1];
            *(float2*)(out + grB + col) = ob;
        }
}

// ---------------- launch ----------------
extern "C" void kernel_launch(void* const* d_in, const int* in_sizes, int n_in,
                              void* d_out, int out_size) {
    const float* x        = (const float*)d_in[0];
    const float* feat     = (const float*)d_in[1];
    const float* attn_mask= (const float*)d_in[2];
    const int*   rel_index= (const int*)  d_in[3];
    const float* rel_tab  = (const float*)d_in[4];
    const float* q_w      = (const float*)d_in[5];
    const float* q_b      = (const float*)d_in[6];
    const float* kv_w     = (const float*)d_in[7];
    const float* kv_b     = (const float*)d_in[8];
    const float* proj_w   = (const float*)d_in[9];
    const float* proj_b   = (const float*)d_in[10];
    const float* merge_w  = (const float*)d_in[11];
    const float* n1g      = (const float*)d_in[12];
    const float* n1b      = (const float*)d_in[13];
    const float* n2g      = (const float*)d_in[14];
    const float* n2b      = (const float*)d_in[15];
    const float* fc1_w    = (const float*)d_in[16];
    const float* fc1_b    = (const float*)d_in[17];
    const float* fc2_w    = (const float*)d_in[18];
    const float* fc2_b    = (const float*)d_in[19];
    float* out = (float*)d_out;

    const int SMEM_ATTN = (2112 * 3 + 4160) * 4;          // 41,984 B
    cudaFuncSetAttribute(k_attn,         cudaFuncAttributeMaxDynamicSharedMemorySize, SMEM_ATTN);
    cudaFuncSetAttribute(k_qkv_tc,       cudaFuncAttributeMaxDynamicSharedMemorySize, QKV_SMEM);
    cudaFuncSetAttribute(k_projmerge_tc, cudaFuncAttributeMaxDynamicSharedMemorySize, PM_SMEM);
    cudaFuncSetAttribute(k_mlp_tc,       cudaFuncAttributeMaxDynamicSharedMemorySize, MLP_SMEM);

    k_transpose<<<dim3(2048, 6, 8), dim3(32, 8)>>>(x, feat);
    k_bias<<<96, 256>>>(rel_index, rel_tab);
    k_wsplit<<<(WTOT + 255) / 256, 256>>>(q_w, kv_w, proj_w, merge_w, fc1_w, fc2_w);
    k_qkv_tc<<<2048, 256, QKV_SMEM>>>(q_b, kv_b);
    k_attn<<<NWIN * NHEAD, 128, SMEM_ATTN>>>(attn_mask);
    k_projmerge_tc<<<2048, 256, PM_SMEM>>>(proj_b, n1g, n1b);
    k_mlp_tc<<<2048, 256, MLP_SMEM>>>(fc1_b, fc2_b, n2g, n2b, out);
}

// round 7
// speedup vs baseline: 2.2767x; 1.5673x over previous
#include <cuda_runtime.h>
#include <cuda_bf16.h>
#include <cstdint>

// ---------------- problem constants ----------------
#define Hh 256
#define Ww 256
#define Bb 4
#define Cc 192
#define NHEAD 6
#define NWIN 4096
#define NTOK 64
#define TOKALL (Bb*Hh*Ww)
#define WINELEM (NTOK*Cc)

// weight-split offsets (elements)
#define OQ  0
#define OKV 36864
#define OP  110592
#define OM  147456
#define OF1 184320
#define OF2 331776
#define WTOT 479232

// ---------------- device scratch ----------------
__device__ float g_xt[(size_t)TOKALL * Cc];
__device__ float g_ft[(size_t)TOKALL * Cc];
__device__ float g_q [(size_t)NWIN * WINELEM];
__device__ float g_k [(size_t)NWIN * WINELEM];
__device__ float g_v [(size_t)NWIN * WINELEM];
__device__ float g_o [(size_t)NWIN * WINELEM];
__device__ float g_x1[(size_t)TOKALL * Cc];
__device__ float g_bias[NHEAD * NTOK * NTOK];
__device__ __align__(16) __nv_bfloat16 g_wh[WTOT];
__device__ __align__(16) __nv_bfloat16 g_wl[WTOT];

// ---------------- helpers ----------------
__device__ __forceinline__ float gelu_fast(float x) {
    float z = x * 0.7071067811865475f;
    float az = fabsf(z);
    float t = __fdividef(1.0f, fmaf(0.3275911f, az, 1.0f));
    float p = t * (0.254829592f + t * (-0.284496736f + t * (1.421413741f +
              t * (-1.453152027f + t * 1.061405429f))));
    float e = __expf(-az * az);
    float erfv = 1.0f - p * e;
    erfv = copysignf(erfv, z);
    return 0.5f * x * (1.0f + erfv);
}

__device__ __forceinline__ uint32_t smem_u32(const void* p) {
    uint32_t a;
    asm("{ .reg .u64 t; cvta.to.shared.u64 t, %1; cvt.u32.u64 %0, t; }" : "=r"(a) : "l"(p));
    return a;
}

__device__ __forceinline__ void split2(float v0, float v1, uint32_t& hp, uint32_t& lp) {
    __nv_bfloat16 h0 = __float2bfloat16(v0);
    __nv_bfloat16 h1 = __float2bfloat16(v1);
    __nv_bfloat16 l0 = __float2bfloat16(v0 - __bfloat162float(h0));
    __nv_bfloat16 l1 = __float2bfloat16(v1 - __bfloat162float(h1));
    hp = (uint32_t)__bfloat16_as_ushort(h0) | ((uint32_t)__bfloat16_as_ushort(h1) << 16);
    lp = (uint32_t)__bfloat16_as_ushort(l0) | ((uint32_t)__bfloat16_as_ushort(l1) << 16);
}

__device__ __forceinline__ void ldsm_x4(uint32_t (&r)[4], uint32_t a) {
    asm volatile("ldmatrix.sync.aligned.m8n8.x4.shared.b16 {%0,%1,%2,%3}, [%4];"
        : "=r"(r[0]), "=r"(r[1]), "=r"(r[2]), "=r"(r[3]) : "r"(a));
}

__device__ __forceinline__ void mma16816(float (&c)[4], const uint32_t (&a)[4],
                                         uint32_t b0, uint32_t b1) {
    asm volatile("mma.sync.aligned.m16n8k16.row.col.f32.bf16.bf16.f32 "
        "{%0,%1,%2,%3}, {%4,%5,%6,%7}, {%8,%9}, {%0,%1,%2,%3};"
        : "+f"(c[0]), "+f"(c[1]), "+f"(c[2]), "+f"(c[3])
        : "r"(a[0]), "r"(a[1]), "r"(a[2]), "r"(a[3]), "r"(b0), "r"(b1));
}

// Warp GEMM: C[16][NT2*16] += A[16][KS*16] @ W^T with bf16 hi/lo split (3 terms)
template<int KS, int NT2, int AS, int WS>
__device__ __forceinline__ void wgemm(uint32_t aH, uint32_t aL,
                                      uint32_t wH, uint32_t wL,
                                      float (*c)[4], int lane) {
    const uint32_t aoff = (uint32_t)(((lane & 15) * AS + ((lane >> 4) << 3)) * 2);
    const uint32_t woff = (uint32_t)(((((lane >> 4) << 3) + (lane & 7)) * WS + (lane & 8)) * 2);
    aH += aoff; aL += aoff; wH += woff; wL += woff;
    #pragma unroll
    for (int ks = 0; ks < KS; ++ks) {
        uint32_t ah[4], al[4];
        ldsm_x4(ah, aH + ks * 32);
        ldsm_x4(al, aL + ks * 32);
        #pragma unroll
        for (int p = 0; p < NT2; ++p) {
            uint32_t bh[4], bl[4];
            ldsm_x4(bh, wH + p * (16 * WS * 2) + ks * 32);
            ldsm_x4(bl, wL + p * (16 * WS * 2) + ks * 32);
            mma16816(c[2*p],   ah, bh[0], bh[1]);
            mma16816(c[2*p],   al, bh[0], bh[1]);
            mma16816(c[2*p],   ah, bl[0], bl[1]);
            mma16816(c[2*p+1], ah, bh[2], bh[3]);
            mma16816(c[2*p+1], al, bh[2], bh[3]);
            mma16816(c[2*p+1], ah, bl[2], bl[3]);
        }
    }
}

// ---------------- cp.async helpers ----------------
__device__ __forceinline__ void cp16(uint32_t d, const void* s) {
    asm volatile("cp.async.cg.shared.global [%0], [%1], 16;" :: "r"(d), "l"(s) : "memory");
}
__device__ __forceinline__ void cp_commit() {
    asm volatile("cp.async.commit_group;" ::: "memory");
}
__device__ __forceinline__ void cp_wait0() {
    asm volatile("cp.async.wait_group 0;" ::: "memory");
}

// async-stage a pre-split weight tile (hi+lo) into smem
__device__ __forceinline__ void cpstageW(uint32_t dh, uint32_t dl,
        const __nv_bfloat16* sh, const __nv_bfloat16* sl,
        int rows, int ku4, int srck, int koff, int dstride, int tid) {
    int tot = rows * ku4;
    for (int i = tid; i < tot; i += 256) {
        int r = i / ku4, q = i - r * ku4;
        size_t s = (size_t)r * srck + koff + q * 8;
        uint32_t d = (uint32_t)(r * dstride + q * 8) * 2;
        cp16(dh + d, sh + s);
        cp16(dl + d, sl + s);
    }
    cp_commit();
}

// stage fp32 activations -> split bf16 hi/lo smem (stride 200)
__device__ __forceinline__ void stage_linear(char* dh, char* dl, const float* src, int tid) {
    for (int i = tid; i < 128 * 96; i += 256) {
        int r = i / 96, cp = (i - r * 96) * 2;
        float2 v = *(const float2*)(src + (size_t)r * 192 + cp);
        uint32_t hp, lp; split2(v.x, v.y, hp, lp);
        size_t d = ((size_t)r * 200 + cp) * 2;
        *(uint32_t*)(dh + d) = hp;
        *(uint32_t*)(dl + d) = lp;
    }
}

// stage with shifted-window gather (roll -4), 2 windows per CTA
__device__ __forceinline__ void stage_gather(char* dh, char* dl, const float* src,
                                             int w0, int tid) {
    for (int i = tid; i < 128 * 96; i += 256) {
        int r = i / 96, cp = (i - r * 96) * 2;
        int win = w0 + (r >> 6);
        int b = win >> 10, wlr = win & 1023, wh = wlr >> 5, ww = wlr & 31;
        int n = r & 63, ii = n >> 3, jj = n & 7;
        int hh = (wh * 8 + ii + 4) & 255, wp = (ww * 8 + jj + 4) & 255;
        size_t off = (((size_t)b * 256 + hh) * 256 + wp) * 192 + cp;
        float2 v = *(const float2*)(src + off);
        uint32_t hp, lp; split2(v.x, v.y, hp, lp);
        size_t d = ((size_t)r * 200 + cp) * 2;
        *(uint32_t*)(dh + d) = hp;
        *(uint32_t*)(dl + d) = lp;
    }
}

// ---------------- kernel 0: NCHW -> NHWC ----------------
__global__ void k_transpose(const float* __restrict__ x, const float* __restrict__ f) {
    __shared__ float tile[32][33];
    int b = blockIdx.z >> 1;
    const float* src = (blockIdx.z & 1) ? f : x;
    float* dst = (blockIdx.z & 1) ? g_ft : g_xt;
    int hw0 = blockIdx.x * 32;
    int c0 = blockIdx.y * 32;
    #pragma unroll
    for (int i = threadIdx.y; i < 32; i += 8)
        tile[i][threadIdx.x] =
            src[((size_t)b * Cc + c0 + i) * (Hh * Ww) + hw0 + threadIdx.x];
    __syncthreads();
    #pragma unroll
    for (int i = threadIdx.y; i < 32; i += 8)
        dst[((size_t)b * (Hh * Ww) + hw0 + i) * Cc + c0 + threadIdx.x] =
            tile[threadIdx.x][i];
}

// ---------------- kernel 1: expand relative-position bias ----------------
__global__ void k_bias(const int* __restrict__ rel_index, const float* __restrict__ table) {
    int idx = blockIdx.x * blockDim.x + threadIdx.x;
    if (idx < NHEAD * NTOK * NTOK) {
        int h = idx / (NTOK * NTOK);
        int nm = idx % (NTOK * NTOK);
        g_bias[idx] = table[rel_index[nm] * NHEAD + h];
    }
}

// ---------------- kernel 1b: split ALL weights to bf16 hi/lo ----------------
__global__ void k_wsplit(const float* __restrict__ q_w, const float* __restrict__ kv_w,
                         const float* __restrict__ proj_w, const float* __restrict__ merge_w,
                         const float* __restrict__ fc1_w, const float* __restrict__ fc2_w) {
    int i = blockIdx.x * 256 + threadIdx.x;
    if (i >= WTOT) return;
    float v;
    if (i < OKV)       v = q_w[i];
    else if (i < OP)   v = kv_w[i - OKV];
    else if (i < OM)   v = proj_w[i - OP];
    else if (i < OF1)  v = merge_w[i - OM];
    else if (i < OF2)  v = fc1_w[i - OF1];
    else               v = fc2_w[i - OF2];
    __nv_bfloat16 h = __float2bfloat16(v);
    g_wh[i] = h;
    g_wl[i] = __float2bfloat16(v - __bfloat162float(h));
}

// ---------------- kernel 2: QKV projections (pipelined mma.sync) ----------------
// smem: Ahi 0 (51200) Alo 51200 | Wbuf0 102400/121600 | Wbuf1 140800/160000
#define QKV_SMEM 179200
__global__ void __launch_bounds__(256, 1)
k_qkv_tc(const float* __restrict__ q_b, const float* __restrict__ kv_b) {
    extern __shared__ char smc[];
    const uint32_t sb = smem_u32(smc);
    char* A_HI = smc; char* A_LO = smc + 51200;
    const uint32_t WBh[2] = {sb + 102400, sb + 140800};
    const uint32_t WBl[2] = {sb + 121600, sb + 160000};
    int tid = threadIdx.x, wid = tid >> 5, lane = tid & 31;
    int gid = lane >> 2, tig = lane & 3;
    size_t tok0 = (size_t)blockIdx.x * 128;
    int w0 = blockIdx.x * 2;
    const uint32_t aW = sb + (uint32_t)(wid * 6400);
    const uint32_t aWl = sb + 51200 + (uint32_t)(wid * 6400);
    const float scale = 0.17677669529663687f;

    cpstageW(WBh[0], WBl[0], g_wh + OQ, g_wl + OQ, 48, 24, 192, 0, 200, tid);
    stage_gather(A_HI, A_LO, g_xt, w0, tid);

    for (int t = 0; t < 12; ++t) {
        cp_wait0();
        __syncthreads();
        if (t < 11) {
            int tn = t + 1, g = tn >> 2, sub = tn & 3;
            size_t off = (g == 0) ? OQ + (size_t)sub * 48 * 192
                       : (g == 1) ? OKV + (size_t)sub * 48 * 192
                                  : OKV + 192 * 192 + (size_t)sub * 48 * 192;
            cpstageW(WBh[tn & 1], WBl[tn & 1], g_wh + off, g_wl + off,
                     48, 24, 192, 0, 200, tid);
        }
        if (t == 4) {
            stage_gather(A_HI, A_LO, g_ft, w0, tid);
            __syncthreads();
        }
        float c[6][4];
        #pragma unroll
        for (int i = 0; i < 6; ++i) { c[i][0]=c[i][1]=c[i][2]=c[i][3]=0.f; }
        wgemm<12, 3, 200, 200>(aW, aWl, WBh[t & 1], WBl[t & 1], c, lane);

        int g = t >> 2, sub = t & 3;
        float* dst = (g == 0) ? g_q : (g == 1) ? g_k : g_v;
        const float* bias = (g == 0) ? q_b : (g == 1) ? kv_b : kv_b + 192;
        float sc = (g == 0) ? scale : 1.f;
        size_t rA = tok0 + wid * 16 + gid;
        #pragma unroll
        for (int nt = 0; nt < 6; ++nt) {
            int col = sub * 48 + nt * 8 + 2 * tig;
            float2 o0 = make_float2((c[nt][0] + bias[col]) * sc, (c[nt][1] + bias[col+1]) * sc);
            float2 o1 = make_float2((c[nt][2] + bias[col]) * sc, (c[nt][3] + bias[col+1]) * sc);
            *(float2*)(dst + rA * 192 + col) = o0;
            *(float2*)(dst + (rA + 8) * 192 + col) = o1;
        }
    }
}

// ---------------- kernel 3: windowed attention (mma.sync, hi/lo split) ----------------
// smem: Qhi 0 Qlo 5120 Khi 10240 Klo 15360 Vthi 20480 Vtlo 25088 Phi 29696 Plo 38912
#define ATTN_SMEM 48128
__global__ void __launch_bounds__(128)
k_attn_tc(const float* __restrict__ mask) {
    extern __shared__ char smc[];
    const uint32_t sb = smem_u32(smc);
    char* c_QHI = smc;           char* c_QLO = smc + 5120;
    char* c_KHI = smc + 10240;   char* c_KLO = smc + 15360;
    char* c_VTH = smc + 20480;   char* c_VTL = smc + 25088;
    char* c_PHI = smc + 29696;   char* c_PLO = smc + 38912;
    int bx = blockIdx.x;
    int wi = bx & 4095;
    int h = bx >> 12;
    int wl = wi & 1023;
    int tid = threadIdx.x, wid = tid >> 5, lane = tid & 31;
    int gid = lane >> 2, tig = lane & 3;
    const size_t base = (size_t)wi * WINELEM + h * 32;

    for (int i = tid; i < 1024; i += 128) {
        int n = i >> 4, dp = (i & 15) * 2;
        float2 q2 = *(const float2*)(g_q + base + n * 192 + dp);
        float2 k2 = *(const float2*)(g_k + base + n * 192 + dp);
        uint32_t hp, lp;
        split2(q2.x, q2.y, hp, lp);
        *(uint32_t*)(c_QHI + (n * 40 + dp) * 2) = hp;
        *(uint32_t*)(c_QLO + (n * 40 + dp) * 2) = lp;
        split2(k2.x, k2.y, hp, lp);
        *(uint32_t*)(c_KHI + (n * 40 + dp) * 2) = hp;
        *(uint32_t*)(c_KLO + (n * 40 + dp) * 2) = lp;
        int key = i & 63, dq = (i >> 6) * 2;
        float2 v2 = *(const float2*)(g_v + base + key * 192 + dq);
        __nv_bfloat16 vh0 = __float2bfloat16(v2.x), vh1 = __float2bfloat16(v2.y);
        __nv_bfloat16 vl0 = __float2bfloat16(v2.x - __bfloat162float(vh0));
        __nv_bfloat16 vl1 = __float2bfloat16(v2.y - __bfloat162float(vh1));
        *(__nv_bfloat16*)(c_VTH + (dq * 72 + key) * 2) = vh0;
        *(__nv_bfloat16*)(c_VTH + ((dq + 1) * 72 + key) * 2) = vh1;
        *(__nv_bfloat16*)(c_VTL + (dq * 72 + key) * 2) = vl0;
        *(__nv_bfloat16*)(c_VTL + ((dq + 1) * 72 + key) * 2) = vl1;
    }
    __syncthreads();

    // QK^T: 16 rows per warp, all 64 keys
    float c[8][4];
    #pragma unroll
    for (int i = 0; i < 8; ++i) { c[i][0]=c[i][1]=c[i][2]=c[i][3]=0.f; }
    wgemm<2, 4, 40, 40>(sb + (uint32_t)(wid * 1280), sb + 5120 + (uint32_t)(wid * 1280),
                        sb + 10240, sb + 15360, c, lane);

    // bias + mask + softmax (rows rA, rB per thread)
    int rA = wid * 16 + gid, rB = rA + 8;
    const float* bg = g_bias + h * 4096;
    const float* mg = mask + (size_t)wl * 4096;
    float vA[16], vB[16];
    #pragma unroll
    for (int nt = 0; nt < 8; ++nt) {
        int col = nt * 8 + 2 * tig;
        float2 b0 = *(const float2*)(bg + rA * 64 + col);
        float2 m0 = *(const float2*)(mg + rA * 64 + col);
        vA[2*nt]   = c[nt][0] + b0.x + m0.x;
        vA[2*nt+1] = c[nt][1] + b0.y + m0.y;
        float2 b1 = *(const float2*)(bg + rB * 64 + col);
        float2 m1 = *(const float2*)(mg + rB * 64 + col);
        vB[2*nt]   = c[nt][2] + b1.x + m1.x;
        vB[2*nt+1] = c[nt][3] + b1.y + m1.y;
    }
    float mxA = -1e30f, mxB = -1e30f;
    #pragma unroll
    for (int j = 0; j < 16; ++j) { mxA = fmaxf(mxA, vA[j]); mxB = fmaxf(mxB, vB[j]); }
    mxA = fmaxf(mxA, __shfl_xor_sync(0xffffffffu, mxA, 1));
    mxA = fmaxf(mxA, __shfl_xor_sync(0xffffffffu, mxA, 2));
    mxB = fmaxf(mxB, __shfl_xor_sync(0xffffffffu, mxB, 1));
    mxB = fmaxf(mxB, __shfl_xor_sync(0xffffffffu, mxB, 2));
    float sA = 0.f, sB = 0.f;
    #pragma unroll
    for (int j = 0; j < 16; ++j) {
        vA[j] = __expf(vA[j] - mxA); sA += vA[j];
        vB[j] = __expf(vB[j] - mxB); sB += vB[j];
    }
    sA += __shfl_xor_sync(0xffffffffu, sA, 1);
    sA += __shfl_xor_sync(0xffffffffu, sA, 2);
    sB += __shfl_xor_sync(0xffffffffu, sB, 1);
    sB += __shfl_xor_sync(0xffffffffu, sB, 2);
    float invA = 1.f / sA, invB = 1.f / sB;
    #pragma unroll
    for (int nt = 0; nt < 8; ++nt) {
        int col = nt * 8 + 2 * tig;
        uint32_t hp, lp;
        split2(vA[2*nt] * invA, vA[2*nt+1] * invA, hp, lp);
        *(uint32_t*)(c_PHI + (rA * 72 + col) * 2) = hp;
        *(uint32_t*)(c_PLO + (rA * 72 + col) * 2) = lp;
        split2(vB[2*nt] * invB, vB[2*nt+1] * invB, hp, lp);
        *(uint32_t*)(c_PHI + (rB * 72 + col) * 2) = hp;
        *(uint32_t*)(c_PLO + (rB * 72 + col) * 2) = lp;
    }
    __syncwarp();

    // P @ V
    float o[4][4];
    #pragma unroll
    for (int i = 0; i < 4; ++i) { o[i][0]=o[i][1]=o[i][2]=o[i][3]=0.f; }
    wgemm<4, 2, 72, 72>(sb + 29696 + (uint32_t)(wid * 2304), sb + 38912 + (uint32_t)(wid * 2304),
                        sb + 20480, sb + 25088, o, lane);

    #pragma unroll
    for (int nt = 0; nt < 4; ++nt) {
        int col = nt * 8 + 2 * tig;
        *(float2*)(g_o + base + (size_t)rA * 192 + col) = make_float2(o[nt][0], o[nt][1]);
        *(float2*)(g_o + base + (size_t)rB * 192 + col) = make_float2(o[nt][2], o[nt][3]);
    }
}

// ---------------- kernel 4: proj -> merge -> LN -> residual (pipelined) ----------------
#define PM_SMEM 179200
__global__ void __launch_bounds__(256, 1)
k_projmerge_tc(const float* __restrict__ proj_b,
               const float* __restrict__ g1, const float* __restrict__ b1) {
    extern __shared__ char smc[];
    const uint32_t sb = smem_u32(smc);
    char* A_HI = smc; char* A_LO = smc + 51200;
    const uint32_t WBh[2] = {sb + 102400, sb + 140800};
    const uint32_t WBl[2] = {sb + 121600, sb + 160000};
    int tid = threadIdx.x, wid = tid >> 5, lane = tid & 31;
    int gid = lane >> 2, tig = lane & 3;
    size_t tok0 = (size_t)blockIdx.x * 128;
    const uint32_t aW = sb + (uint32_t)(wid * 6400);
    const uint32_t aWl = sb + 51200 + (uint32_t)(wid * 6400);
    int lrA = wid * 16 + gid, lrB = lrA + 8;

    cpstageW(WBh[0], WBl[0], g_wh + OP, g_wl + OP, 48, 24, 192, 0, 200, tid);
    stage_linear(A_HI, A_LO, g_o + tok0 * 192, tid);

    float c1[24][4], c2[24][4];
    #pragma unroll
    for (int i = 0; i < 24; ++i) { c1[i][0]=c1[i][1]=c1[i][2]=c1[i][3]=0.f;
                                   c2[i][0]=c2[i][1]=c2[i][2]=c2[i][3]=0.f; }

    for (int t = 0; t < 8; ++t) {
        cp_wait0();
        __syncthreads();
        if (t < 7) {
            int tn = t + 1;
            size_t off = (tn < 4) ? OP + (size_t)tn * 48 * 192
                                  : OM + (size_t)(tn - 4) * 48 * 192;
            cpstageW(WBh[tn & 1], WBl[tn & 1], g_wh + off, g_wl + off,
                     48, 24, 192, 0, 200, tid);
        }
        if (t == 4) {
            // rewrite A <- split(Y) : each warp touches only its own rows
            #pragma unroll
            for (int tt = 0; tt < 4; ++tt)
                #pragma unroll
                for (int nt = 0; nt < 6; ++nt) {
                    int col = tt * 48 + nt * 8 + 2 * tig;
                    uint32_t hp, lp;
                    split2(c1[tt*6+nt][0] + proj_b[col], c1[tt*6+nt][1] + proj_b[col+1], hp, lp);
                    size_t dA = ((size_t)lrA * 200 + col) * 2;
                    *(uint32_t*)(A_HI + dA) = hp; *(uint32_t*)(A_LO + dA) = lp;
                    split2(c1[tt*6+nt][2] + proj_b[col], c1[tt*6+nt][3] + proj_b[col+1], hp, lp);
                    size_t dB = ((size_t)lrB * 200 + col) * 2;
                    *(uint32_t*)(A_HI + dB) = hp; *(uint32_t*)(A_LO + dB) = lp;
                }
            __syncwarp();
        }
        float (*cc)[4] = (t < 4) ? (c1 + t * 6) : (c2 + (t - 4) * 6);
        wgemm<12, 3, 200, 200>(aW, aWl, WBh[t & 1], WBl[t & 1], cc, lane);
    }

    // LN + roll/scatter + residual
    float sA = 0.f, qA = 0.f, sB = 0.f, qB = 0.f;
    #pragma unroll
    for (int i = 0; i < 24; ++i) {
        sA += c2[i][0] + c2[i][1];
        qA += c2[i][0]*c2[i][0] + c2[i][1]*c2[i][1];
        sB += c2[i][2] + c2[i][3];
        qB += c2[i][2]*c2[i][2] + c2[i][3]*c2[i][3];
    }
    #pragma unroll
    for (int d = 1; d <= 2; d <<= 1) {
        sA += __shfl_xor_sync(0xffffffffu, sA, d);
        qA += __shfl_xor_sync(0xffffffffu, qA, d);
        sB += __shfl_xor_sync(0xffffffffu, sB, d);
        qB += __shfl_xor_sync(0xffffffffu, qB, d);
    }
    float muA = sA * (1.f/192.f), rsA = rsqrtf(qA * (1.f/192.f) - muA*muA + 1e-5f);
    float muB = sB * (1.f/192.f), rsB = rsqrtf(qB * (1.f/192.f) - muB*muB + 1e-5f);

    auto rowoff = [&](int lr) -> size_t {
        int win = blockIdx.x * 2 + (lr >> 6);
        int b = win >> 10, wlr = win & 1023, wh = wlr >> 5, ww = wlr & 31;
        int n = lr & 63, ii = n >> 3, jj = n & 7;
        int hf = (wh * 8 + ii + 4) & 255, wf = (ww * 8 + jj + 4) & 255;
        return (((size_t)b * 256 + hf) * 256 + wf) * 192;
    };
    size_t roA = rowoff(lrA), roB = rowoff(lrB);

    #pragma unroll
    for (int tt = 0; tt < 4; ++tt)
        #pragma unroll
        for (int nt = 0; nt < 6; ++nt) {
            int col = tt * 48 + nt * 8 + 2 * tig;
            int i = tt * 6 + nt;
            float2 xa = *(const float2*)(g_xt + roA + col);
            float2 za;
            za.x = xa.x + (c2[i][0] - muA) * rsA * g1[col]   + b1[col];
            za.y = xa.y + (c2[i][1] - muA) * rsA * g1[col+1] + b1[col+1];
            *(float2*)(g_x1 + roA + col) = za;
            float2 xb = *(const float2*)(g_xt + roB + col);
            float2 zb;
            zb.x = xb.x + (c2[i][2] - muB) * rsB * g1[col]   + b1[col];
            zb.y = xb.y + (c2[i][3] - muB) * rsB * g1[col+1] + b1[col+1];
            *(float2*)(g_x1 + roB + col) = zb;
        }
}

// ---------------- kernel 5: MLP + LN + residual (pipelined) ----------------
// smem: Ahi 0 Alo 51200 | Hhi 102400 Hlo 120832 | Wb0 139264/152064 Wb1 164864/177664
#define MLP_SMEM 190464
__global__ void __launch_bounds__(256, 1)
k_mlp_tc(const float* __restrict__ fc1_b, const float* __restrict__ fc2_b,
         const float* __restrict__ g2, const float* __restrict__ b2,
         float* __restrict__ out) {
    extern __shared__ char smc[];
    const uint32_t sb = smem_u32(smc);
    char* A_HI = smc; char* A_LO = smc + 51200;
    char* H_HI = smc + 102400; char* H_LO = smc + 120832;
    const uint32_t WBh[2] = {sb + 139264, sb + 164864};
    const uint32_t WBl[2] = {sb + 152064, sb + 177664};
    int tid = threadIdx.x, wid = tid >> 5, lane = tid & 31;
    int gid = lane >> 2, tig = lane & 3;
    size_t tok0 = (size_t)blockIdx.x * 128;
    const uint32_t aW = sb + (uint32_t)(wid * 6400);
    const uint32_t aWl = sb + 51200 + (uint32_t)(wid * 6400);
    const uint32_t hW = sb + 102400 + (uint32_t)(wid * 2304);
    const uint32_t hWl = sb + 120832 + (uint32_t)(wid * 2304);
    int lrA = wid * 16 + gid, lrB = lrA + 8;

    cpstageW(WBh[0], WBl[0], g_wh + OF1, g_wl + OF1, 32, 24, 192, 0, 200, tid);
    stage_linear(A_HI, A_LO, g_x1 + tok0 * 192, tid);

    // fc2 accumulators: 3 phases x NT2=4 -> 8 accs per phase, 24 total (192 cols)
    float cf2[24][4];
    #pragma unroll
    for (int i = 0; i < 24; ++i) { cf2[i][0]=cf2[i][1]=cf2[i][2]=cf2[i][3]=0.f; }

    int pidx = 0;
    for (int ck = 0; ck < 12; ++ck) {
        for (int ph = 0; ph < 5; ++ph, ++pidx) {
            cp_wait0();
            __syncthreads();
            int nck = ck, nph = ph + 1;
            if (nph == 5) { nph = 0; ++nck; }
            if (nck < 12) {
                int par = (pidx + 1) & 1;
                if (nph < 2)
                    cpstageW(WBh[par], WBl[par],
                             g_wh + OF1 + ((size_t)nck * 64 + nph * 32) * 192,
                             g_wl + OF1 + ((size_t)nck * 64 + nph * 32) * 192,
                             32, 24, 192, 0, 200, tid);
                else
                    cpstageW(WBh[par], WBl[par],
                             g_wh + OF2 + (size_t)(nph - 2) * 64 * 768,
                             g_wl + OF2 + (size_t)(nph - 2) * 64 * 768,
                             64, 8, 768, nck * 64, 72, tid);
            }
            int par = pidx & 1;
            if (ph < 2) {
                float c1[4][4];
                #pragma unroll
                for (int i = 0; i < 4; ++i) { c1[i][0]=c1[i][1]=c1[i][2]=c1[i][3]=0.f; }
                wgemm<12, 2, 200, 200>(aW, aWl, WBh[par], WBl[par], c1, lane);
                #pragma unroll
                for (int nt = 0; nt < 4; ++nt) {
                    int col = ph * 32 + nt * 8 + 2 * tig;
                    int bc = ck * 64 + col;
                    uint32_t hp, lp;
                    split2(gelu_fast(c1[nt][0] + fc1_b[bc]),
                           gelu_fast(c1[nt][1] + fc1_b[bc+1]), hp, lp);
                    size_t dA = ((size_t)lrA * 72 + col) * 2;
                    *(uint32_t*)(H_HI + dA) = hp; *(uint32_t*)(H_LO + dA) = lp;
                    split2(gelu_fast(c1[nt][2] + fc1_b[bc]),
                           gelu_fast(c1[nt][3] + fc1_b[bc+1]), hp, lp);
                    size_t dB = ((size_t)lrB * 72 + col) * 2;
                    *(uint32_t*)(H_HI + dB) = hp; *(uint32_t*)(H_LO + dB) = lp;
                }
                __syncwarp();
            } else {
                // 64 staged W2 rows -> NT2=4 (64 output cols) per phase
                wgemm<4, 4, 72, 72>(hW, hWl, WBh[par], WBl[par], cf2 + (ph - 2) * 8, lane);
            }
        }
    }

    // LN + residual epilogue: phase p covers cols [p*64, p*64+64)
    float sA = 0.f, qA = 0.f, sB = 0.f, qB = 0.f;
    #pragma unroll
    for (int p = 0; p < 3; ++p)
        #pragma unroll
        for (int nt = 0; nt < 8; ++nt) {
            int col = p * 64 + nt * 8 + 2 * tig;
            int i = p * 8 + nt;
            float z0 = cf2[i][0] + fc2_b[col];
            float z1 = cf2[i][1] + fc2_b[col+1];
            float z2 = cf2[i][2] + fc2_b[col];
            float z3 = cf2[i][3] + fc2_b[col+1];
            sA += z0 + z1; qA += z0*z0 + z1*z1;
            sB += z2 + z3; qB += z2*z2 + z3*z3;
        }
    #pragma unroll
    for (int d = 1; d <= 2; d <<= 1) {
        sA += __shfl_xor_sync(0xffffffffu, sA, d);
        qA += __shfl_xor_sync(0xffffffffu, qA, d);
        sB += __shfl_xor_sync(0xffffffffu, sB, d);
        qB += __shfl_xor_sync(0xffffffffu, qB, d);
    }
    float muA = sA * (1.f/192.f), rsA = rsqrtf(qA * (1.f/192.f) - muA*muA + 1e-5f);
    float muB = sB * (1.f/192.f), rsB = rsqrtf(qB * (1.f/192.f) - muB*muB + 1e-5f);

    size_t grA = (tok0 + lrA) * 192, grB = (tok0 + lrB) * 192;
    #pragma unroll
    for (int p = 0; p < 3; ++p)
        #pragma unroll
        for (int nt = 0; nt < 8; ++nt) {
            int col = p * 64 + nt * 8 + 2 * tig;
            int i = p * 8 + nt;
            float z0 = cf2[i][0] + fc2_b[col];
            float z1 = cf2[i][1] + fc2_b[col+1];
            float z2 = cf2[i][2] + fc2_b[col];
            float z3 = cf2[i][3] + fc2_b[col+1];
            float2 xa = *(const float2*)(g_x1 + grA + col);
            float2 oa;
            oa.x = xa.x + (z0 - muA) * rsA * g2[col]   + b2[col];
            oa.y = xa.y + (z1 - muA) * rsA * g2[col+1] + b2[col+1];
            *(float2*)(out + grA + col) = oa;
            float2 xb = *(const float2*)(g_x1 + grB + col);
            float2 ob;
            ob.x = xb.x + (z2 - muB) * rsB * g2[col]   + b2[col];
            ob.y = xb.y + (z3 - muB) * rsB * g2[col+1] + b2[col+1];
            *(float2*)(out + grB + col) = ob;
        }
}

// ---------------- launch ----------------
extern "C" void kernel_launch(void* const* d_in, const int* in_sizes, int n_in,
                              void* d_out, int out_size) {
    const float* x        = (const float*)d_in[0];
    const float* feat     = (const float*)d_in[1];
    const float* attn_mask= (const float*)d_in[2];
    const int*   rel_index= (const int*)  d_in[3];
    const float* rel_tab  = (const float*)d_in[4];
    const float* q_w      = (const float*)d_in[5];
    const float* q_b      = (const float*)d_in[6];
    const float* kv_w     = (const float*)d_in[7];
    const float* kv_b     = (const float*)d_in[8];
    const float* proj_w   = (const float*)d_in[9];
    const float* proj_b   = (const float*)d_in[10];
    const float* merge_w  = (const float*)d_in[11];
    const float* n1g      = (const float*)d_in[12];
    const float* n1b      = (const float*)d_in[13];
    const float* n2g      = (const float*)d_in[14];
    const float* n2b      = (const float*)d_in[15];
    const float* fc1_w    = (const float*)d_in[16];
    const float* fc1_b    = (const float*)d_in[17];
    const float* fc2_w    = (const float*)d_in[18];
    const float* fc2_b    = (const float*)d_in[19];
    float* out = (float*)d_out;

    cudaFuncSetAttribute(k_qkv_tc,       cudaFuncAttributeMaxDynamicSharedMemorySize, QKV_SMEM);
    cudaFuncSetAttribute(k_attn_tc,      cudaFuncAttributeMaxDynamicSharedMemorySize, ATTN_SMEM);
    cudaFuncSetAttribute(k_projmerge_tc, cudaFuncAttributeMaxDynamicSharedMemorySize, PM_SMEM);
    cudaFuncSetAttribute(k_mlp_tc,       cudaFuncAttributeMaxDynamicSharedMemorySize, MLP_SMEM);

    k_transpose<<<dim3(2048, 6, 8), dim3(32, 8)>>>(x, feat);
    k_bias<<<96, 256>>>(rel_index, rel_tab);
    k_wsplit<<<(WTOT + 255) / 256, 256>>>(q_w, kv_w, proj_w, merge_w, fc1_w, fc2_w);
    k_qkv_tc<<<2048, 256, QKV_SMEM>>>(q_b, kv_b);
    k_attn_tc<<<NWIN * NHEAD, 128, ATTN_SMEM>>>(attn_mask);
    k_projmerge_tc<<<2048, 256, PM_SMEM>>>(proj_b, n1g, n1b);
    k_mlp_tc<<<2048, 256, MLP_SMEM>>>(fc1_b, fc2_b, n2g, n2b, out);
}

// round 8
// speedup vs baseline: 2.2833x; 1.0029x over previous
#include <cuda_runtime.h>
#include <cuda_bf16.h>
#include <cstdint>

// ---------------- problem constants ----------------
#define Hh 256
#define Ww 256
#define Bb 4
#define Cc 192
#define NHEAD 6
#define NWIN 4096
#define NTOK 64
#define TOKALL (Bb*Hh*Ww)
#define WINELEM (NTOK*Cc)

// weight-split offsets (elements)
#define OQ  0
#define OKV 36864
#define OP  110592
#define OM  147456
#define OF1 184320
#define OF2 331776
#define WTOT 479232

// ---------------- device scratch ----------------
__device__ float g_xt[(size_t)TOKALL * Cc];
__device__ float g_ft[(size_t)TOKALL * Cc];
__device__ float g_q [(size_t)NWIN * WINELEM];
__device__ float g_k [(size_t)NWIN * WINELEM];
__device__ float g_v [(size_t)NWIN * WINELEM];
__device__ float g_o [(size_t)NWIN * WINELEM];
__device__ float g_x1[(size_t)TOKALL * Cc];
__device__ float g_bias[NHEAD * NTOK * NTOK];
__device__ __align__(16) __nv_bfloat16 g_wh[WTOT];
__device__ __align__(16) __nv_bfloat16 g_wl[WTOT];

// ---------------- helpers ----------------
__device__ __forceinline__ float gelu_fast(float x) {
    float z = x * 0.7071067811865475f;
    float az = fabsf(z);
    float t = __fdividef(1.0f, fmaf(0.3275911f, az, 1.0f));
    float p = t * (0.254829592f + t * (-0.284496736f + t * (1.421413741f +
              t * (-1.453152027f + t * 1.061405429f))));
    float e = __expf(-az * az);
    float erfv = 1.0f - p * e;
    erfv = copysignf(erfv, z);
    return 0.5f * x * (1.0f + erfv);
}

__device__ __forceinline__ uint32_t smem_u32(const void* p) {
    uint32_t a;
    asm("{ .reg .u64 t; cvta.to.shared.u64 t, %1; cvt.u32.u64 %0, t; }" : "=r"(a) : "l"(p));
    return a;
}

__device__ __forceinline__ void split2(float v0, float v1, uint32_t& hp, uint32_t& lp) {
    __nv_bfloat16 h0 = __float2bfloat16(v0);
    __nv_bfloat16 h1 = __float2bfloat16(v1);
    __nv_bfloat16 l0 = __float2bfloat16(v0 - __bfloat162float(h0));
    __nv_bfloat16 l1 = __float2bfloat16(v1 - __bfloat162float(h1));
    hp = (uint32_t)__bfloat16_as_ushort(h0) | ((uint32_t)__bfloat16_as_ushort(h1) << 16);
    lp = (uint32_t)__bfloat16_as_ushort(l0) | ((uint32_t)__bfloat16_as_ushort(l1) << 16);
}

__device__ __forceinline__ void ldsm_x4(uint32_t (&r)[4], uint32_t a) {
    asm volatile("ldmatrix.sync.aligned.m8n8.x4.shared.b16 {%0,%1,%2,%3}, [%4];"
        : "=r"(r[0]), "=r"(r[1]), "=r"(r[2]), "=r"(r[3]) : "r"(a));
}

__device__ __forceinline__ void mma16816(float (&c)[4], const uint32_t (&a)[4],
                                         uint32_t b0, uint32_t b1) {
    asm volatile("mma.sync.aligned.m16n8k16.row.col.f32.bf16.bf16.f32 "
        "{%0,%1,%2,%3}, {%4,%5,%6,%7}, {%8,%9}, {%0,%1,%2,%3};"
        : "+f"(c[0]), "+f"(c[1]), "+f"(c[2]), "+f"(c[3])
        : "r"(a[0]), "r"(a[1]), "r"(a[2]), "r"(a[3]), "r"(b0), "r"(b1));
}

// Warp GEMM: C[16][NT2*16] += A[16][KS*16] @ W^T with bf16 hi/lo split (3 terms)
template<int KS, int NT2, int AS, int WS>
__device__ __forceinline__ void wgemm(uint32_t aH, uint32_t aL,
                                      uint32_t wH, uint32_t wL,
                                      float (*c)[4], int lane) {
    const uint32_t aoff = (uint32_t)(((lane & 15) * AS + ((lane >> 4) << 3)) * 2);
    const uint32_t woff = (uint32_t)(((((lane >> 4) << 3) + (lane & 7)) * WS + (lane & 8)) * 2);
    aH += aoff; aL += aoff; wH += woff; wL += woff;
    #pragma unroll
    for (int ks = 0; ks < KS; ++ks) {
        uint32_t ah[4], al[4];
        ldsm_x4(ah, aH + ks * 32);
        ldsm_x4(al, aL + ks * 32);
        #pragma unroll
        for (int p = 0; p < NT2; ++p) {
            uint32_t bh[4], bl[4];
            ldsm_x4(bh, wH + p * (16 * WS * 2) + ks * 32);
            ldsm_x4(bl, wL + p * (16 * WS * 2) + ks * 32);
            mma16816(c[2*p],   ah, bh[0], bh[1]);
            mma16816(c[2*p],   al, bh[0], bh[1]);
            mma16816(c[2*p],   ah, bl[0], bl[1]);
            mma16816(c[2*p+1], ah, bh[2], bh[3]);
            mma16816(c[2*p+1], al, bh[2], bh[3]);
            mma16816(c[2*p+1], ah, bl[2], bl[3]);
        }
    }
}

// ---------------- cp.async helpers ----------------
__device__ __forceinline__ void cp16(uint32_t d, const void* s) {
    asm volatile("cp.async.cg.shared.global [%0], [%1], 16;" :: "r"(d), "l"(s) : "memory");
}
__device__ __forceinline__ void cp_commit() {
    asm volatile("cp.async.commit_group;" ::: "memory");
}
__device__ __forceinline__ void cp_wait0() {
    asm volatile("cp.async.wait_group 0;" ::: "memory");
}

// async-stage a pre-split weight tile (hi+lo) into smem (512-thread CTAs)
__device__ __forceinline__ void cpstageW(uint32_t dh, uint32_t dl,
        const __nv_bfloat16* sh, const __nv_bfloat16* sl,
        int rows, int ku4, int srck, int koff, int dstride, int tid) {
    int tot = rows * ku4;
    for (int i = tid; i < tot; i += 512) {
        int r = i / ku4, q = i - r * ku4;
        size_t s = (size_t)r * srck + koff + q * 8;
        uint32_t d = (uint32_t)(r * dstride + q * 8) * 2;
        cp16(dh + d, sh + s);
        cp16(dl + d, sl + s);
    }
    cp_commit();
}

// stage fp32 activations -> split bf16 hi/lo smem (stride 200), 512 threads
__device__ __forceinline__ void stage_linear(char* dh, char* dl, const float* src, int tid) {
    for (int i = tid; i < 128 * 96; i += 512) {
        int r = i / 96, cp = (i - r * 96) * 2;
        float2 v = *(const float2*)(src + (size_t)r * 192 + cp);
        uint32_t hp, lp; split2(v.x, v.y, hp, lp);
        size_t d = ((size_t)r * 200 + cp) * 2;
        *(uint32_t*)(dh + d) = hp;
        *(uint32_t*)(dl + d) = lp;
    }
}

// stage with shifted-window gather (roll -4), 2 windows per CTA, 512 threads
__device__ __forceinline__ void stage_gather(char* dh, char* dl, const float* src,
                                             int w0, int tid) {
    for (int i = tid; i < 128 * 96; i += 512) {
        int r = i / 96, cp = (i - r * 96) * 2;
        int win = w0 + (r >> 6);
        int b = win >> 10, wlr = win & 1023, wh = wlr >> 5, ww = wlr & 31;
        int n = r & 63, ii = n >> 3, jj = n & 7;
        int hh = (wh * 8 + ii + 4) & 255, wp = (ww * 8 + jj + 4) & 255;
        size_t off = (((size_t)b * 256 + hh) * 256 + wp) * 192 + cp;
        float2 v = *(const float2*)(src + off);
        uint32_t hp, lp; split2(v.x, v.y, hp, lp);
        size_t d = ((size_t)r * 200 + cp) * 2;
        *(uint32_t*)(dh + d) = hp;
        *(uint32_t*)(dl + d) = lp;
    }
}

// ---------------- kernel 0: NCHW -> NHWC ----------------
__global__ void k_transpose(const float* __restrict__ x, const float* __restrict__ f) {
    __shared__ float tile[32][33];
    int b = blockIdx.z >> 1;
    const float* src = (blockIdx.z & 1) ? f : x;
    float* dst = (blockIdx.z & 1) ? g_ft : g_xt;
    int hw0 = blockIdx.x * 32;
    int c0 = blockIdx.y * 32;
    #pragma unroll
    for (int i = threadIdx.y; i < 32; i += 8)
        tile[i][threadIdx.x] =
            src[((size_t)b * Cc + c0 + i) * (Hh * Ww) + hw0 + threadIdx.x];
    __syncthreads();
    #pragma unroll
    for (int i = threadIdx.y; i < 32; i += 8)
        dst[((size_t)b * (Hh * Ww) + hw0 + i) * Cc + c0 + threadIdx.x] =
            tile[threadIdx.x][i];
}

// ---------------- kernel 1: expand relative-position bias ----------------
__global__ void k_bias(const int* __restrict__ rel_index, const float* __restrict__ table) {
    int idx = blockIdx.x * blockDim.x + threadIdx.x;
    if (idx < NHEAD * NTOK * NTOK) {
        int h = idx / (NTOK * NTOK);
        int nm = idx % (NTOK * NTOK);
        g_bias[idx] = table[rel_index[nm] * NHEAD + h];
    }
}

// ---------------- kernel 1b: split ALL weights to bf16 hi/lo ----------------
__global__ void k_wsplit(const float* __restrict__ q_w, const float* __restrict__ kv_w,
                         const float* __restrict__ proj_w, const float* __restrict__ merge_w,
                         const float* __restrict__ fc1_w, const float* __restrict__ fc2_w) {
    int i = blockIdx.x * 256 + threadIdx.x;
    if (i >= WTOT) return;
    float v;
    if (i < OKV)       v = q_w[i];
    else if (i < OP)   v = kv_w[i - OKV];
    else if (i < OM)   v = proj_w[i - OP];
    else if (i < OF1)  v = merge_w[i - OM];
    else if (i < OF2)  v = fc1_w[i - OF1];
    else               v = fc2_w[i - OF2];
    __nv_bfloat16 h = __float2bfloat16(v);
    g_wh[i] = h;
    g_wl[i] = __float2bfloat16(v - __bfloat162float(h));
}

// ---------------- kernel 2: QKV projections (512 thr, 16 warps) ----------------
// smem: Ahi 0 Alo 51200 | WB0 hi 102400 lo 128000 | WB1 hi 153600 lo 179200
#define QKV_SMEM 204800
__global__ void __launch_bounds__(512, 1)
k_qkv_tc(const float* __restrict__ q_b, const float* __restrict__ kv_b) {
    extern __shared__ char smc[];
    const uint32_t sb = smem_u32(smc);
    char* A_HI = smc; char* A_LO = smc + 51200;
    const uint32_t WBh[2] = {sb + 102400, sb + 153600};
    const uint32_t WBl[2] = {sb + 128000, sb + 179200};
    int tid = threadIdx.x, wid = tid >> 5, lane = tid & 31;
    int rb = wid & 7, ch = wid >> 3;
    int gid = lane >> 2, tig = lane & 3;
    size_t tok0 = (size_t)blockIdx.x * 128;
    int w0 = blockIdx.x * 2;
    const uint32_t aW  = sb + (uint32_t)(rb * 6400);
    const uint32_t aWl = sb + 51200 + (uint32_t)(rb * 6400);
    const uint32_t wch = (uint32_t)(ch * 12800);   // 32 rows * 400B
    const float scale = 0.17677669529663687f;

    cpstageW(WBh[0], WBl[0], g_wh + OQ, g_wl + OQ, 64, 24, 192, 0, 200, tid);
    stage_gather(A_HI, A_LO, g_xt, w0, tid);

    for (int t = 0; t < 9; ++t) {
        cp_wait0();
        __syncthreads();
        if (t < 8) {
            int tn = t + 1;
            size_t off = (tn < 3) ? OQ + (size_t)tn * 64 * 192
                       : (tn < 6) ? OKV + (size_t)(tn - 3) * 64 * 192
                                  : OKV + 36864 + (size_t)(tn - 6) * 64 * 192;
            cpstageW(WBh[tn & 1], WBl[tn & 1], g_wh + off, g_wl + off,
                     64, 24, 192, 0, 200, tid);
        }
        if (t == 3) {
            stage_gather(A_HI, A_LO, g_ft, w0, tid);
            __syncthreads();
        }
        float c[4][4];
        #pragma unroll
        for (int i = 0; i < 4; ++i) { c[i][0]=c[i][1]=c[i][2]=c[i][3]=0.f; }
        wgemm<12, 2, 200, 200>(aW, aWl, WBh[t & 1] + wch, WBl[t & 1] + wch, c, lane);

        int g = t / 3, sub = t % 3;
        float* dst = (g == 0) ? g_q : (g == 1) ? g_k : g_v;
        const float* bias = (g == 0) ? q_b : (g == 1) ? kv_b : kv_b + 192;
        float sc = (g == 0) ? scale : 1.f;
        size_t rA = tok0 + rb * 16 + gid;
        #pragma unroll
        for (int nt = 0; nt < 4; ++nt) {
            int col = sub * 64 + ch * 32 + nt * 8 + 2 * tig;
            float2 o0 = make_float2((c[nt][0] + bias[col]) * sc, (c[nt][1] + bias[col+1]) * sc);
            float2 o1 = make_float2((c[nt][2] + bias[col]) * sc, (c[nt][3] + bias[col+1]) * sc);
            *(float2*)(dst + rA * 192 + col) = o0;
            *(float2*)(dst + (rA + 8) * 192 + col) = o1;
        }
    }
}

// ---------------- kernel 3: windowed attention (mma.sync, hi/lo split) ----------------
#define ATTN_SMEM 48128
__global__ void __launch_bounds__(128)
k_attn_tc(const float* __restrict__ mask) {
    extern __shared__ char smc[];
    const uint32_t sb = smem_u32(smc);
    char* c_QHI = smc;           char* c_QLO = smc + 5120;
    char* c_KHI = smc + 10240;   char* c_KLO = smc + 15360;
    char* c_VTH = smc + 20480;   char* c_VTL = smc + 25088;
    char* c_PHI = smc + 29696;   char* c_PLO = smc + 38912;
    int bx = blockIdx.x;
    int wi = bx & 4095;
    int h = bx >> 12;
    int wl = wi & 1023;
    int tid = threadIdx.x, wid = tid >> 5, lane = tid & 31;
    int gid = lane >> 2, tig = lane & 3;
    const size_t base = (size_t)wi * WINELEM + h * 32;

    for (int i = tid; i < 1024; i += 128) {
        int n = i >> 4, dp = (i & 15) * 2;
        float2 q2 = *(const float2*)(g_q + base + n * 192 + dp);
        float2 k2 = *(const float2*)(g_k + base + n * 192 + dp);
        uint32_t hp, lp;
        split2(q2.x, q2.y, hp, lp);
        *(uint32_t*)(c_QHI + (n * 40 + dp) * 2) = hp;
        *(uint32_t*)(c_QLO + (n * 40 + dp) * 2) = lp;
        split2(k2.x, k2.y, hp, lp);
        *(uint32_t*)(c_KHI + (n * 40 + dp) * 2) = hp;
        *(uint32_t*)(c_KLO + (n * 40 + dp) * 2) = lp;
        int key = i & 63, dq = (i >> 6) * 2;
        float2 v2 = *(const float2*)(g_v + base + key * 192 + dq);
        __nv_bfloat16 vh0 = __float2bfloat16(v2.x), vh1 = __float2bfloat16(v2.y);
        __nv_bfloat16 vl0 = __float2bfloat16(v2.x - __bfloat162float(vh0));
        __nv_bfloat16 vl1 = __float2bfloat16(v2.y - __bfloat162float(vh1));
        *(__nv_bfloat16*)(c_VTH + (dq * 72 + key) * 2) = vh0;
        *(__nv_bfloat16*)(c_VTH + ((dq + 1) * 72 + key) * 2) = vh1;
        *(__nv_bfloat16*)(c_VTL + (dq * 72 + key) * 2) = vl0;
        *(__nv_bfloat16*)(c_VTL + ((dq + 1) * 72 + key) * 2) = vl1;
    }
    __syncthreads();

    float c[8][4];
    #pragma unroll
    for (int i = 0; i < 8; ++i) { c[i][0]=c[i][1]=c[i][2]=c[i][3]=0.f; }
    wgemm<2, 4, 40, 40>(sb + (uint32_t)(wid * 1280), sb + 5120 + (uint32_t)(wid * 1280),
                        sb + 10240, sb + 15360, c, lane);

    int rA = wid * 16 + gid, rB = rA + 8;
    const float* bg = g_bias + h * 4096;
    const float* mg = mask + (size_t)wl * 4096;
    float vA[16], vB[16];
    #pragma unroll
    for (int nt = 0; nt < 8; ++nt) {
        int col = nt * 8 + 2 * tig;
        float2 b0 = *(const float2*)(bg + rA * 64 + col);
        float2 m0 = *(const float2*)(mg + rA * 64 + col);
        vA[2*nt]   = c[nt][0] + b0.x + m0.x;
        vA[2*nt+1] = c[nt][1] + b0.y + m0.y;
        float2 b1 = *(const float2*)(bg + rB * 64 + col);
        float2 m1 = *(const float2*)(mg + rB * 64 + col);
        vB[2*nt]   = c[nt][2] + b1.x + m1.x;
        vB[2*nt+1] = c[nt][3] + b1.y + m1.y;
    }
    float mxA = -1e30f, mxB = -1e30f;
    #pragma unroll
    for (int j = 0; j < 16; ++j) { mxA = fmaxf(mxA, vA[j]); mxB = fmaxf(mxB, vB[j]); }
    mxA = fmaxf(mxA, __shfl_xor_sync(0xffffffffu, mxA, 1));
    mxA = fmaxf(mxA, __shfl_xor_sync(0xffffffffu, mxA, 2));
    mxB = fmaxf(mxB, __shfl_xor_sync(0xffffffffu, mxB, 1));
    mxB = fmaxf(mxB, __shfl_xor_sync(0xffffffffu, mxB, 2));
    float sA = 0.f, sB = 0.f;
    #pragma unroll
    for (int j = 0; j < 16; ++j) {
        vA[j] = __expf(vA[j] - mxA); sA += vA[j];
        vB[j] = __expf(vB[j] - mxB); sB += vB[j];
    }
    sA += __shfl_xor_sync(0xffffffffu, sA, 1);
    sA += __shfl_xor_sync(0xffffffffu, sA, 2);
    sB += __shfl_xor_sync(0xffffffffu, sB, 1);
    sB += __shfl_xor_sync(0xffffffffu, sB, 2);
    float invA = 1.f / sA, invB = 1.f / sB;
    #pragma unroll
    for (int nt = 0; nt < 8; ++nt) {
        int col = nt * 8 + 2 * tig;
        uint32_t hp, lp;
        split2(vA[2*nt] * invA, vA[2*nt+1] * invA, hp, lp);
        *(uint32_t*)(c_PHI + (rA * 72 + col) * 2) = hp;
        *(uint32_t*)(c_PLO + (rA * 72 + col) * 2) = lp;
        split2(vB[2*nt] * invB, vB[2*nt+1] * invB, hp, lp);
        *(uint32_t*)(c_PHI + (rB * 72 + col) * 2) = hp;
        *(uint32_t*)(c_PLO + (rB * 72 + col) * 2) = lp;
    }
    __syncwarp();

    float o[4][4];
    #pragma unroll
    for (int i = 0; i < 4; ++i) { o[i][0]=o[i][1]=o[i][2]=o[i][3]=0.f; }
    wgemm<4, 2, 72, 72>(sb + 29696 + (uint32_t)(wid * 2304), sb + 38912 + (uint32_t)(wid * 2304),
                        sb + 20480, sb + 25088, o, lane);

    #pragma unroll
    for (int nt = 0; nt < 4; ++nt) {
        int col = nt * 8 + 2 * tig;
        *(float2*)(g_o + base + (size_t)rA * 192 + col) = make_float2(o[nt][0], o[nt][1]);
        *(float2*)(g_o + base + (size_t)rB * 192 + col) = make_float2(o[nt][2], o[nt][3]);
    }
}

// ---------------- kernel 4: proj -> merge -> LN -> residual (512 thr) ----------------
#define PM_SMEM 204800
__global__ void __launch_bounds__(512, 1)
k_projmerge_tc(const float* __restrict__ proj_b,
               const float* __restrict__ g1, const float* __restrict__ b1) {
    extern __shared__ char smc[];
    const uint32_t sb = smem_u32(smc);
    char* A_HI = smc; char* A_LO = smc + 51200;
    const uint32_t WBh[2] = {sb + 102400, sb + 153600};
    const uint32_t WBl[2] = {sb + 128000, sb + 179200};
    int tid = threadIdx.x, wid = tid >> 5, lane = tid & 31;
    int rb = wid & 7, ch = wid >> 3;
    int gid = lane >> 2, tig = lane & 3;
    size_t tok0 = (size_t)blockIdx.x * 128;
    const uint32_t aW  = sb + (uint32_t)(rb * 6400);
    const uint32_t aWl = sb + 51200 + (uint32_t)(rb * 6400);
    const uint32_t wch = (uint32_t)(ch * 12800);
    int lrA = rb * 16 + gid, lrB = lrA + 8;

    cpstageW(WBh[0], WBl[0], g_wh + OP, g_wl + OP, 64, 24, 192, 0, 200, tid);
    stage_linear(A_HI, A_LO, g_o + tok0 * 192, tid);

    float c1[12][4], c2[12][4];
    #pragma unroll
    for (int i = 0; i < 12; ++i) { c1[i][0]=c1[i][1]=c1[i][2]=c1[i][3]=0.f;
                                   c2[i][0]=c2[i][1]=c2[i][2]=c2[i][3]=0.f; }

    for (int t = 0; t < 6; ++t) {
        cp_wait0();
        __syncthreads();
        if (t < 5) {
            int tn = t + 1;
            size_t off = (tn < 3) ? OP + (size_t)tn * 64 * 192
                                  : OM + (size_t)(tn - 3) * 64 * 192;
            cpstageW(WBh[tn & 1], WBl[tn & 1], g_wh + off, g_wl + off,
                     64, 24, 192, 0, 200, tid);
        }
        if (t == 3) {
            // A <- split(Y): warp writes its rows x its 96 cols
            #pragma unroll
            for (int tt = 0; tt < 3; ++tt)
                #pragma unroll
                for (int nt = 0; nt < 4; ++nt) {
                    int col = tt * 64 + ch * 32 + nt * 8 + 2 * tig;
                    int i = tt * 4 + nt;
                    uint32_t hp, lp;
                    split2(c1[i][0] + proj_b[col], c1[i][1] + proj_b[col+1], hp, lp);
                    size_t dA = ((size_t)lrA * 200 + col) * 2;
                    *(uint32_t*)(A_HI + dA) = hp; *(uint32_t*)(A_LO + dA) = lp;
                    split2(c1[i][2] + proj_b[col], c1[i][3] + proj_b[col+1], hp, lp);
                    size_t dB = ((size_t)lrB * 200 + col) * 2;
                    *(uint32_t*)(A_HI + dB) = hp; *(uint32_t*)(A_LO + dB) = lp;
                }
            __syncthreads();   // partner warp's cols must land before merge GEMM
        }
        float (*cc)[4] = (t < 3) ? (c1 + t * 4) : (c2 + (t - 3) * 4);
        wgemm<12, 2, 200, 200>(aW, aWl, WBh[t & 1] + wch, WBl[t & 1] + wch, cc, lane);
    }

    // LN: cross-warp-pair partial reduce via smem (reuse dead W region)
    float sA = 0.f, qA = 0.f, sB = 0.f, qB = 0.f;
    #pragma unroll
    for (int i = 0; i < 12; ++i) {
        sA += c2[i][0] + c2[i][1];
        qA += c2[i][0]*c2[i][0] + c2[i][1]*c2[i][1];
        sB += c2[i][2] + c2[i][3];
        qB += c2[i][2]*c2[i][2] + c2[i][3]*c2[i][3];
    }
    #pragma unroll
    for (int d = 1; d <= 2; d <<= 1) {
        sA += __shfl_xor_sync(0xffffffffu, sA, d);
        qA += __shfl_xor_sync(0xffffffffu, qA, d);
        sB += __shfl_xor_sync(0xffffffffu, sB, d);
        qB += __shfl_xor_sync(0xffffffffu, qB, d);
    }
    float2* red = (float2*)(smc + 102400);  // [ch][row] -> (s,q)
    __syncthreads();
    if (tig == 0) {
        red[ch * 128 + lrA] = make_float2(sA, qA);
        red[ch * 128 + lrB] = make_float2(sB, qB);
    }
    __syncthreads();
    float2 pA0 = red[lrA], pA1 = red[128 + lrA];
    float2 pB0 = red[lrB], pB1 = red[128 + lrB];
    float muA = (pA0.x + pA1.x) * (1.f/192.f);
    float rsA = rsqrtf((pA0.y + pA1.y) * (1.f/192.f) - muA*muA + 1e-5f);
    float muB = (pB0.x + pB1.x) * (1.f/192.f);
    float rsB = rsqrtf((pB0.y + pB1.y) * (1.f/192.f) - muB*muB + 1e-5f);

    auto rowoff = [&](int lr) -> size_t {
        int win = blockIdx.x * 2 + (lr >> 6);
        int b = win >> 10, wlr = win & 1023, wh = wlr >> 5, ww = wlr & 31;
        int n = lr & 63, ii = n >> 3, jj = n & 7;
        int hf = (wh * 8 + ii + 4) & 255, wf = (ww * 8 + jj + 4) & 255;
        return (((size_t)b * 256 + hf) * 256 + wf) * 192;
    };
    size_t roA = rowoff(lrA), roB = rowoff(lrB);

    #pragma unroll
    for (int tt = 0; tt < 3; ++tt)
        #pragma unroll
        for (int nt = 0; nt < 4; ++nt) {
            int col = tt * 64 + ch * 32 + nt * 8 + 2 * tig;
            int i = tt * 4 + nt;
            float2 xa = *(const float2*)(g_xt + roA + col);
            float2 za;
            za.x = xa.x + (c2[i][0] - muA) * rsA * g1[col]   + b1[col];
            za.y = xa.y + (c2[i][1] - muA) * rsA * g1[col+1] + b1[col+1];
            *(float2*)(g_x1 + roA + col) = za;
            float2 xb = *(const float2*)(g_xt + roB + col);
            float2 zb;
            zb.x = xb.x + (c2[i][2] - muB) * rsB * g1[col]   + b1[col];
            zb.y = xb.y + (c2[i][3] - muB) * rsB * g1[col+1] + b1[col+1];
            *(float2*)(g_x1 + roB + col) = zb;
        }
}

// ---------------- kernel 5: MLP + LN + residual (512 thr, 4-phase pipeline) ----------------
// smem: Ahi 0 Alo 51200 | Hhi 102400 Hlo 120832 |
//       WB0 hi 139264 lo 153088 | WB1 hi 166912 lo 180736   (slot hi cap 13824)
#define MLP_SMEM 194560
__global__ void __launch_bounds__(512, 1)
k_mlp_tc(const float* __restrict__ fc1_b, const float* __restrict__ fc2_b,
         const float* __restrict__ g2, const float* __restrict__ b2,
         float* __restrict__ out) {
    extern __shared__ char smc[];
    const uint32_t sb = smem_u32(smc);
    char* A_HI = smc; char* A_LO = smc + 51200;
    char* H_HI = smc + 102400; char* H_LO = smc + 120832;
    const uint32_t WBh[2] = {sb + 139264, sb + 166912};
    const uint32_t WBl[2] = {sb + 153088, sb + 180736};
    int tid = threadIdx.x, wid = tid >> 5, lane = tid & 31;
    int rb = wid & 7, ch = wid >> 3;
    int gid = lane >> 2, tig = lane & 3;
    size_t tok0 = (size_t)blockIdx.x * 128;
    const uint32_t aW  = sb + (uint32_t)(rb * 6400);
    const uint32_t aWl = sb + 51200 + (uint32_t)(rb * 6400);
    const uint32_t hW  = sb + 102400 + (uint32_t)(rb * 16 * 144);
    const uint32_t hWl = sb + 120832 + (uint32_t)(rb * 16 * 144);
    const uint32_t w1ch = (uint32_t)(ch * 6656);   // 32 rows * 208B
    const uint32_t w2ch = (uint32_t)(ch * 6912);   // 48 rows * 144B
    int lrA = rb * 16 + gid, lrB = lrA + 8;

    cpstageW(WBh[0], WBl[0], g_wh + OF1, g_wl + OF1, 64, 12, 192, 0, 104, tid);
    stage_linear(A_HI, A_LO, g_x1 + tok0 * 192, tid);

    float cf2[12][4];
    #pragma unroll
    for (int i = 0; i < 12; ++i) { cf2[i][0]=cf2[i][1]=cf2[i][2]=cf2[i][3]=0.f; }
    float c1[4][4];

    for (int pidx = 0; pidx < 48; ++pidx) {
        int ck = pidx >> 2, ph = pidx & 3;
        cp_wait0();
        __syncthreads();
        int np = pidx + 1, nck = np >> 2, nph = np & 3;
        if (nck < 12) {
            int par = np & 1;
            if (nph < 2)
                cpstageW(WBh[par], WBl[par],
                         g_wh + OF1 + (size_t)nck * 64 * 192,
                         g_wl + OF1 + (size_t)nck * 64 * 192,
                         64, 12, 192, nph * 96, 104, tid);
            else
                cpstageW(WBh[par], WBl[par],
                         g_wh + OF2 + (size_t)(nph - 2) * 96 * 768,
                         g_wl + OF2 + (size_t)(nph - 2) * 96 * 768,
                         96, 8, 768, nck * 64, 72, tid);
        }
        int par = pidx & 1;
        if (ph < 2) {
            if (ph == 0) {
                #pragma unroll
                for (int i = 0; i < 4; ++i) { c1[i][0]=c1[i][1]=c1[i][2]=c1[i][3]=0.f; }
            }
            // fc1 K-half: A k-offset ph*96 elems (192B), W1 tile 64x96 @ stride 104
            wgemm<6, 2, 200, 104>(aW + ph * 192, aWl + ph * 192,
                                  WBh[par] + w1ch, WBl[par] + w1ch, c1, lane);
            if (ph == 1) {
                #pragma unroll
                for (int nt = 0; nt < 4; ++nt) {
                    int col = ch * 32 + nt * 8 + 2 * tig;
                    int bc = ck * 64 + col;
                    uint32_t hp, lp;
                    split2(gelu_fast(c1[nt][0] + fc1_b[bc]),
                           gelu_fast(c1[nt][1] + fc1_b[bc+1]), hp, lp);
                    size_t dA = ((size_t)lrA * 72 + col) * 2;
                    *(uint32_t*)(H_HI + dA) = hp; *(uint32_t*)(H_LO + dA) = lp;
                    split2(gelu_fast(c1[nt][2] + fc1_b[bc]),
                           gelu_fast(c1[nt][3] + fc1_b[bc+1]), hp, lp);
                    size_t dB = ((size_t)lrB * 72 + col) * 2;
                    *(uint32_t*)(H_HI + dB) = hp; *(uint32_t*)(H_LO + dB) = lp;
                }
            }
        } else {
            // fc2 tile (96 output rows): warp covers ch*48..+48 within tile
            wgemm<4, 3, 72, 72>(hW, hWl, WBh[par] + w2ch, WBl[par] + w2ch,
                                cf2 + (ph - 2) * 6, lane);
        }
    }

    // LN + residual (cross-warp-pair reduce via smem)
    float sA = 0.f, qA = 0.f, sB = 0.f, qB = 0.f;
    float zr[12][4];
    #pragma unroll
    for (int p = 0; p < 2; ++p)
        #pragma unroll
        for (int nt = 0; nt < 6; ++nt) {
            int col = p * 96 + ch * 48 + nt * 8 + 2 * tig;
            int i = p * 6 + nt;
            zr[i][0] = cf2[i][0] + fc2_b[col];
            zr[i][1] = cf2[i][1] + fc2_b[col+1];
            zr[i][2] = cf2[i][2] + fc2_b[col];
            zr[i][3] = cf2[i][3] + fc2_b[col+1];
            sA += zr[i][0] + zr[i][1]; qA += zr[i][0]*zr[i][0] + zr[i][1]*zr[i][1];
            sB += zr[i][2] + zr[i][3]; qB += zr[i][2]*zr[i][2] + zr[i][3]*zr[i][3];
        }
    #pragma unroll
    for (int d = 1; d <= 2; d <<= 1) {
        sA += __shfl_xor_sync(0xffffffffu, sA, d);
        qA += __shfl_xor_sync(0xffffffffu, qA, d);
        sB += __shfl_xor_sync(0xffffffffu, sB, d);
        qB += __shfl_xor_sync(0xffffffffu, qB, d);
    }
    float2* red = (float2*)(smc + 139264);
    __syncthreads();
    if (tig == 0) {
        red[ch * 128 + lrA] = make_float2(sA, qA);
        red[ch * 128 + lrB] = make_float2(sB, qB);
    }
    __syncthreads();
    float2 pA0 = red[lrA], pA1 = red[128 + lrA];
    float2 pB0 = red[lrB], pB1 = red[128 + lrB];
    float muA = (pA0.x + pA1.x) * (1.f/192.f);
    float rsA = rsqrtf((pA0.y + pA1.y) * (1.f/192.f) - muA*muA + 1e-5f);
    float muB = (pB0.x + pB1.x) * (1.f/192.f);
    float rsB = rsqrtf((pB0.y + pB1.y) * (1.f/192.f) - muB*muB + 1e-5f);

    size_t grA = (tok0 + lrA) * 192, grB = (tok0 + lrB) * 192;
    #pragma unroll
    for (int p = 0; p < 2; ++p)
        #pragma unroll
        for (int nt = 0; nt < 6; ++nt) {
            int col = p * 96 + ch * 48 + nt * 8 + 2 * tig;
            int i = p * 6 + nt;
            float2 xa = *(const float2*)(g_x1 + grA + col);
            float2 oa;
            oa.x = xa.x + (zr[i][0] - muA) * rsA * g2[col]   + b2[col];
            oa.y = xa.y + (zr[i][1] - muA) * rsA * g2[col+1] + b2[col+1];
            *(float2*)(out + grA + col) = oa;
            float2 xb = *(const float2*)(g_x1 + grB + col);
            float2 ob;
            ob.x = xb.x + (zr[i][2] - muB) * rsB * g2[col]   + b2[col];
            ob.y = xb.y + (zr[i][3] - muB) * rsB * g2[col+1] + b2[col+1];
            *(float2*)(out + grB + col) = ob;
        }
}

// ---------------- launch ----------------
extern "C" void kernel_launch(void* const* d_in, const int* in_sizes, int n_in,
                              void* d_out, int out_size) {
    const float* x        = (const float*)d_in[0];
    const float* feat     = (const float*)d_in[1];
    const float* attn_mask= (const float*)d_in[2];
    const int*   rel_index= (const int*)  d_in[3];
    const float* rel_tab  = (const float*)d_in[4];
    const float* q_w      = (const float*)d_in[5];
    const float* q_b      = (const float*)d_in[6];
    const float* kv_w     = (const float*)d_in[7];
    const float* kv_b     = (const float*)d_in[8];
    const float* proj_w   = (const float*)d_in[9];
    const float* proj_b   = (const float*)d_in[10];
    const float* merge_w  = (const float*)d_in[11];
    const float* n1g      = (const float*)d_in[12];
    const float* n1b      = (const float*)d_in[13];
    const float* n2g      = (const float*)d_in[14];
    const float* n2b      = (const float*)d_in[15];
    const float* fc1_w    = (const float*)d_in[16];
    const float* fc1_b    = (const float*)d_in[17];
    const float* fc2_w    = (const float*)d_in[18];
    const float* fc2_b    = (const float*)d_in[19];
    float* out = (float*)d_out;

    cudaFuncSetAttribute(k_qkv_tc,       cudaFuncAttributeMaxDynamicSharedMemorySize, QKV_SMEM);
    cudaFuncSetAttribute(k_attn_tc,      cudaFuncAttributeMaxDynamicSharedMemorySize, ATTN_SMEM);
    cudaFuncSetAttribute(k_projmerge_tc, cudaFuncAttributeMaxDynamicSharedMemorySize, PM_SMEM);
    cudaFuncSetAttribute(k_mlp_tc,       cudaFuncAttributeMaxDynamicSharedMemorySize, MLP_SMEM);

    k_transpose<<<dim3(2048, 6, 8), dim3(32, 8)>>>(x, feat);
    k_bias<<<96, 256>>>(rel_index, rel_tab);
    k_wsplit<<<(WTOT + 255) / 256, 256>>>(q_w, kv_w, proj_w, merge_w, fc1_w, fc2_w);
    k_qkv_tc<<<2048, 512, QKV_SMEM>>>(q_b, kv_b);
    k_attn_tc<<<NWIN * NHEAD, 128, ATTN_SMEM>>>(attn_mask);
    k_projmerge_tc<<<2048, 512, PM_SMEM>>>(proj_b, n1g, n1b);
    k_mlp_tc<<<2048, 512, MLP_SMEM>>>(fc1_b, fc2_b, n2g, n2b, out);
}